// round 5
// baseline (speedup 1.0000x reference)
#include <cuda_runtime.h>
#include <cstdint>

#define NND 4096
#define EMAX 131072
#define ETMAX (EMAX + NND)

// ---------------- device scratch (static globals: allocation-free) ----------------
__device__ __align__(16) float g_h1[(size_t)NND * 512];
__device__ __align__(16) float g_hact[(size_t)NND * 512];
__device__ __align__(16) float g_h2[(size_t)NND * 256];
__device__ __align__(16) float g_res[(size_t)NND * 256];
__device__ __align__(16) float g_A2[(size_t)NND * NND];
__device__ __align__(16) unsigned char g_A[(size_t)NND * NND];
__device__ __align__(16) unsigned char g_AT[(size_t)NND * NND];
__device__ int g_degout[NND], g_degin[NND], g_degdst[NND];
__device__ int g_rpout[NND + 1], g_rpin[NND + 1], g_rpdst[NND + 1];
__device__ int g_colout[ETMAX + 64], g_colin[ETMAX + 64];
__device__ int g_eid[ETMAX + 64];
__device__ int g_cnt[NND];
__device__ float g_mw[ETMAX];
__device__ float g_rs[NND];
__device__ float g_outdegf[NND];
__device__ float g_s1s[NND * 8], g_s1d[NND * 8];
__device__ float g_s2s[NND], g_s2d[NND];
__device__ float g_alpha1[(size_t)ETMAX * 8];
__device__ float g_alpha2[ETMAX];

// ---------------- zero fill ----------------
__global__ void k_zero() {
    size_t i0 = (size_t)blockIdx.x * blockDim.x + threadIdx.x;
    size_t stride = (size_t)gridDim.x * blockDim.x;
    float4 zf = make_float4(0.f, 0.f, 0.f, 0.f);
    int4 zi = make_int4(0, 0, 0, 0);
    float4* a2 = (float4*)g_A2;
    for (size_t i = i0; i < (size_t)NND * NND / 4; i += stride) a2[i] = zf;
    int4* a = (int4*)g_A;
    for (size_t i = i0; i < (size_t)NND * NND / 16; i += stride) a[i] = zi;
    int4* at = (int4*)g_AT;
    for (size_t i = i0; i < (size_t)NND * NND / 16; i += stride) at[i] = zi;
    if (i0 < NND) { g_degdst[i0] = 0; g_cnt[i0] = 0; }
}

// ---------------- SGEMM body: C[M,N] = A[M,K] @ B[K,N] ----------------
#define BM 128
#define BN 64
#define BK 16
__device__ __forceinline__ void sgemm_body(const float* __restrict__ A,
                                           const float* __restrict__ B,
                                           float* __restrict__ C,
                                           int N, int K) {
    __shared__ float As[BK][BM + 4];
    __shared__ float Bs[BK][BN];
    const int bm = blockIdx.y * BM, bn = blockIdx.x * BN;
    const int tid = threadIdx.x;
    const int tx = tid & 15, ty = tid >> 4;
    float acc[8][4];
#pragma unroll
    for (int i = 0; i < 8; i++)
#pragma unroll
        for (int j = 0; j < 4; j++) acc[i][j] = 0.f;

    for (int k0 = 0; k0 < K; k0 += BK) {
#pragma unroll
        for (int i = 0; i < 2; i++) {
            int idx = tid + 256 * i;
            int r = idx >> 2, kq = (idx & 3) * 4;
            float4 v = *(const float4*)&A[(size_t)(bm + r) * K + k0 + kq];
            As[kq + 0][r] = v.x; As[kq + 1][r] = v.y;
            As[kq + 2][r] = v.z; As[kq + 3][r] = v.w;
        }
        {
            int r = tid >> 4, nq = (tid & 15) * 4;
            float4 v = *(const float4*)&B[(size_t)(k0 + r) * N + bn + nq];
            *(float4*)&Bs[r][nq] = v;
        }
        __syncthreads();
#pragma unroll
        for (int kk = 0; kk < BK; kk++) {
            float av[8], bv[4];
#pragma unroll
            for (int i = 0; i < 8; i++) av[i] = As[kk][ty * 8 + i];
#pragma unroll
            for (int j = 0; j < 4; j++) bv[j] = Bs[kk][tx * 4 + j];
#pragma unroll
            for (int i = 0; i < 8; i++)
#pragma unroll
                for (int j = 0; j < 4; j++) acc[i][j] += av[i] * bv[j];
        }
        __syncthreads();
    }
#pragma unroll
    for (int i = 0; i < 8; i++) {
        float4 v = make_float4(acc[i][0], acc[i][1], acc[i][2], acc[i][3]);
        *(float4*)&C[(size_t)(bm + ty * 8 + i) * N + bn + tx * 4] = v;
    }
}

__global__ __launch_bounds__(256) void k_gemm1(const float* __restrict__ x,
                                               const float* __restrict__ W1) {
    sgemm_body(x, W1, g_h1, 512, 512);
}
__global__ __launch_bounds__(256) void k_gemm2(const float* __restrict__ W2) {
    sgemm_body(g_hact, W2, g_h2, 256, 512);
}
__global__ __launch_bounds__(256) void k_gemm3(const float* __restrict__ resW2) {
    sgemm_body(g_hact, resW2, g_res, 256, 512);
}

// ---------------- graph build (edge_index is int32: [2, E] row-major) ----------
__global__ void k_edges(const int* __restrict__ ei, int E) {
    int e = blockIdx.x * blockDim.x + threadIdx.x;
    int ET = E + NND;
    if (e >= ET) return;
    int s, d;
    if (e < E) { s = ei[e] & (NND - 1); d = ei[E + e] & (NND - 1); }
    else       { s = e - E; d = s; }
    g_A[(size_t)s * NND + d] = 1;
    g_AT[(size_t)d * NND + s] = 1;
    atomicAdd(&g_degdst[d], 1);
}

__global__ void k_rowcount(int sel) {
    const unsigned char* M = sel ? g_AT : g_A;
    int* deg = sel ? g_degin : g_degout;
    int row = blockIdx.x * 8 + (threadIdx.x >> 5);
    int lane = threadIdx.x & 31;
    const uint32_t* r = (const uint32_t*)(M + (size_t)row * NND);
    int cnt = 0;
    for (int i = lane; i < NND / 4; i += 32) {
        uint32_t u = r[i];
        cnt += (int)((u * 0x01010101u) >> 24);
    }
#pragma unroll
    for (int o = 16; o; o >>= 1) cnt += __shfl_down_sync(~0u, cnt, o);
    if (!lane) deg[row] = cnt;
}

__global__ void k_scan(int sel) {
    const int* deg = (sel == 0) ? g_degout : (sel == 1) ? g_degin : g_degdst;
    int* rp = (sel == 0) ? g_rpout : (sel == 1) ? g_rpin : g_rpdst;
    __shared__ int sh[1024];
    int t = threadIdx.x;
    int a0 = deg[t * 4], a1 = deg[t * 4 + 1], a2 = deg[t * 4 + 2], a3 = deg[t * 4 + 3];
    int tot = a0 + a1 + a2 + a3;
    sh[t] = tot;
    __syncthreads();
    int val = tot;
    for (int off = 1; off < 1024; off <<= 1) {
        int x = (t >= off) ? sh[t - off] : 0;
        __syncthreads();
        val += x;
        sh[t] = val;
        __syncthreads();
    }
    int excl = val - tot;
    rp[t * 4] = excl;
    rp[t * 4 + 1] = excl + a0;
    rp[t * 4 + 2] = excl + a0 + a1;
    rp[t * 4 + 3] = excl + a0 + a1 + a2;
    if (t == 1023) rp[NND] = val;
}

__global__ void k_rowfill(int sel) {
    const unsigned char* M = sel ? g_AT : g_A;
    const int* rp = sel ? g_rpin : g_rpout;
    int* col = sel ? g_colin : g_colout;
    int row = blockIdx.x * 8 + (threadIdx.x >> 5);
    int lane = threadIdx.x & 31;
    const unsigned char* r = M + (size_t)row * NND;
    int base = rp[row];
    for (int i0 = 0; i0 < NND; i0 += 32) {
        int v = r[i0 + lane];
        unsigned mask = __ballot_sync(~0u, v != 0);
        if (v) col[base + __popc(mask & ((1u << lane) - 1u))] = i0 + lane;
        base += __popc(mask);
    }
}

__global__ void k_scatter(const int* __restrict__ ei, int E) {
    int e = blockIdx.x * blockDim.x + threadIdx.x;
    int ET = E + NND;
    if (e >= ET) return;
    int d = (e < E) ? (ei[E + e] & (NND - 1)) : e - E;
    int pos = atomicAdd(&g_cnt[d], 1);
    g_eid[g_rpdst[d] + pos] = e;
}

// ---------------- motif path counting ----------------
__global__ void k_a2() {
    int k = blockIdx.x;
    int ib = g_rpin[k], ni = g_rpin[k + 1] - ib;
    int ob = g_rpout[k], no = g_rpout[k + 1] - ob;
    int tot = ni * no;
    for (int idx = threadIdx.x; idx < tot; idx += blockDim.x) {
        int i = g_colin[ib + idx / no];
        int l = g_colout[ob + idx % no];
        atomicAdd(&g_A2[(size_t)i * NND + l], 1.0f);
    }
}

__global__ void k_outdegf() {
    int i = blockIdx.x * blockDim.x + threadIdx.x;
    if (i < NND) g_outdegf[i] = (float)(g_rpout[i + 1] - g_rpout[i]);
}

__global__ void k_rowsum() {
    int row = blockIdx.x, t = threadIdx.x;
    const float* r = g_A2 + (size_t)row * NND;
    float s = 0.f;
    for (int j = t; j < NND; j += 256) s += r[j] * g_outdegf[j];
    __shared__ float sh[256];
    sh[t] = s; __syncthreads();
    for (int o = 128; o; o >>= 1) { if (t < o) sh[t] += sh[t + o]; __syncthreads(); }
    if (!t) g_rs[row] = fmaxf(sh[0], 1.0f);
}

__global__ void k_mw(const int* __restrict__ ei, int E) {
    int e = blockIdx.x * blockDim.x + threadIdx.x;
    int ET = E + NND;
    if (e >= ET) return;
    int s_, d_;
    if (e < E) { s_ = ei[e] & (NND - 1); d_ = ei[E + e] & (NND - 1); }
    else       { s_ = e - E; d_ = s_; }
    const float* row = g_A2 + (size_t)s_ * NND;
    float acc = 0.f;
    int pb = g_rpin[d_], pe = g_rpin[d_ + 1];
    for (int p = pb; p < pe; p++) acc += row[g_colin[p]];
    g_mw[e] = acc / g_rs[s_];
}

// ---------------- attention ----------------
__global__ void k_s1(const float* __restrict__ as1, const float* __restrict__ ad1) {
    int idx = blockIdx.x * blockDim.x + threadIdx.x;
    if (idx >= NND * 8) return;
    int n = idx >> 3, h = idx & 7;
    const float* hr = g_h1 + (size_t)n * 512 + h * 64;
    const float* a = as1 + h * 64;
    const float* ad = ad1 + h * 64;
    float s = 0.f, d = 0.f;
#pragma unroll
    for (int c = 0; c < 64; c++) { float v = hr[c]; s += v * a[c]; d += v * ad[c]; }
    g_s1s[idx] = s; g_s1d[idx] = d;
}

__device__ __forceinline__ float leaky(float x) { return x > 0.f ? x : 0.2f * x; }

__global__ void k_attn1(const int* __restrict__ ei, int E) {
    int n = blockIdx.x;
    int h = threadIdx.x >> 5, lane = threadIdx.x & 31;
    int b = g_rpdst[n], deg = g_rpdst[n + 1] - b;
    float sd = g_s1d[n * 8 + h];
    float m1 = -1e30f, m2 = -1e30f;
    for (int p = lane; p < deg; p += 32) {
        int e = g_eid[b + p];
        int s_ = (e < E) ? (ei[e] & (NND - 1)) : n;
        float ev = g_s1s[s_ * 8 + h] + sd;
        m1 = fmaxf(m1, leaky(ev));
        m2 = fmaxf(m2, leaky(ev * g_mw[e]));
    }
#pragma unroll
    for (int o = 16; o; o >>= 1) {
        m1 = fmaxf(m1, __shfl_xor_sync(~0u, m1, o));
        m2 = fmaxf(m2, __shfl_xor_sync(~0u, m2, o));
    }
    float S1 = 0.f, S2 = 0.f;
    for (int p = lane; p < deg; p += 32) {
        int e = g_eid[b + p];
        int s_ = (e < E) ? (ei[e] & (NND - 1)) : n;
        float ev = g_s1s[s_ * 8 + h] + sd;
        S1 += expf(leaky(ev) - m1);
        S2 += expf(leaky(ev * g_mw[e]) - m2);
    }
#pragma unroll
    for (int o = 16; o; o >>= 1) {
        S1 += __shfl_xor_sync(~0u, S1, o);
        S2 += __shfl_xor_sync(~0u, S2, o);
    }
    float r1 = 1.0f / (S1 + 1e-16f), r2 = 1.0f / (S2 + 1e-16f);
    for (int p = lane; p < deg; p += 32) {
        int e = g_eid[b + p];
        int s_ = (e < E) ? (ei[e] & (NND - 1)) : n;
        float ev = g_s1s[s_ * 8 + h] + sd;
        float a1 = expf(leaky(ev) - m1) * r1;
        float a2 = expf(leaky(ev * g_mw[e]) - m2) * r2;
        g_alpha1[(size_t)e * 8 + h] = 0.5f * a1 + 0.5f * a2;
    }
}

__global__ void k_agg1(const int* __restrict__ ei,
                       const float* __restrict__ b1, int E) {
    int n = blockIdx.x, t = threadIdx.x;
    int c = t * 2, h = c >> 6;
    float a0 = 0.f, a1v = 0.f;
    int b = g_rpdst[n], en = g_rpdst[n + 1];
    for (int p = b; p < en; p++) {
        int e = g_eid[p];
        int s_ = (e < E) ? (ei[e] & (NND - 1)) : n;
        float al = g_alpha1[(size_t)e * 8 + h];
        float2 v = *(const float2*)(g_h1 + (size_t)s_ * 512 + c);
        a0 += al * v.x; a1v += al * v.y;
    }
    a0 += b1[c]; a1v += b1[c + 1];
    g_hact[(size_t)n * 512 + c]     = a0  > 0.f ? a0  : expm1f(a0);
    g_hact[(size_t)n * 512 + c + 1] = a1v > 0.f ? a1v : expm1f(a1v);
}

__global__ void k_s2(const float* __restrict__ as2, const float* __restrict__ ad2) {
    int n = blockIdx.x, t = threadIdx.x;
    float v = g_h2[(size_t)n * 256 + t];
    __shared__ float shs[256], shd[256];
    shs[t] = v * as2[t]; shd[t] = v * ad2[t];
    __syncthreads();
    for (int o = 128; o; o >>= 1) {
        if (t < o) { shs[t] += shs[t + o]; shd[t] += shd[t + o]; }
        __syncthreads();
    }
    if (!t) { g_s2s[n] = shs[0]; g_s2d[n] = shd[0]; }
}

__global__ void k_attn2(const int* __restrict__ ei, int E) {
    int n = blockIdx.x * 8 + (threadIdx.x >> 5);
    int lane = threadIdx.x & 31;
    if (n >= NND) return;
    int b = g_rpdst[n], deg = g_rpdst[n + 1] - b;
    float sd = g_s2d[n];
    float m1 = -1e30f, m2 = -1e30f;
    for (int p = lane; p < deg; p += 32) {
        int e = g_eid[b + p];
        int s_ = (e < E) ? (ei[e] & (NND - 1)) : n;
        float ev = g_s2s[s_] + sd;
        m1 = fmaxf(m1, leaky(ev));
        m2 = fmaxf(m2, leaky(ev * g_mw[e]));
    }
#pragma unroll
    for (int o = 16; o; o >>= 1) {
        m1 = fmaxf(m1, __shfl_xor_sync(~0u, m1, o));
        m2 = fmaxf(m2, __shfl_xor_sync(~0u, m2, o));
    }
    float S1 = 0.f, S2 = 0.f;
    for (int p = lane; p < deg; p += 32) {
        int e = g_eid[b + p];
        int s_ = (e < E) ? (ei[e] & (NND - 1)) : n;
        float ev = g_s2s[s_] + sd;
        S1 += expf(leaky(ev) - m1);
        S2 += expf(leaky(ev * g_mw[e]) - m2);
    }
#pragma unroll
    for (int o = 16; o; o >>= 1) {
        S1 += __shfl_xor_sync(~0u, S1, o);
        S2 += __shfl_xor_sync(~0u, S2, o);
    }
    float r1 = 1.0f / (S1 + 1e-16f), r2 = 1.0f / (S2 + 1e-16f);
    for (int p = lane; p < deg; p += 32) {
        int e = g_eid[b + p];
        int s_ = (e < E) ? (ei[e] & (NND - 1)) : n;
        float ev = g_s2s[s_] + sd;
        float a1 = expf(leaky(ev) - m1) * r1;
        float a2 = expf(leaky(ev * g_mw[e]) - m2) * r2;
        g_alpha2[e] = 0.5f * a1 + 0.5f * a2;
    }
}

__global__ void k_agg2(const int* __restrict__ ei,
                       const float* __restrict__ b2, float* __restrict__ out, int E) {
    int n = blockIdx.x, t = threadIdx.x;
    float acc = 0.f;
    int b = g_rpdst[n], en = g_rpdst[n + 1];
    for (int p = b; p < en; p++) {
        int e = g_eid[p];
        int s_ = (e < E) ? (ei[e] & (NND - 1)) : n;
        acc += g_alpha2[e] * g_h2[(size_t)s_ * 256 + t];
    }
    out[(size_t)n * 256 + t] = acc + g_res[(size_t)n * 256 + t] + b2[t];
}

// ---------------- host ----------------
extern "C" void kernel_launch(void* const* d_in, const int* in_sizes, int n_in,
                              void* d_out, int out_size) {
    const float* x      = (const float*)d_in[0];
    const int* ei       = (const int*)d_in[1];   // int32 edge_index [2, E]
    const float* W1     = (const float*)d_in[2];
    const float* as1    = (const float*)d_in[3];
    const float* ad1    = (const float*)d_in[4];
    const float* b1     = (const float*)d_in[5];
    const float* W2     = (const float*)d_in[6];
    const float* as2    = (const float*)d_in[7];
    const float* ad2    = (const float*)d_in[8];
    const float* b2     = (const float*)d_in[9];
    const float* resW2  = (const float*)d_in[10];
    float* out = (float*)d_out;

    int E = in_sizes[1] / 2;
    if (E > EMAX) E = EMAX;
    int ET = E + NND;
    int ETB = (ET + 255) / 256;

    k_zero<<<4736, 256>>>();

    k_gemm1<<<dim3(512 / BN, NND / BM), 256>>>(x, W1);

    k_edges<<<ETB, 256>>>(ei, E);
    k_rowcount<<<NND / 8, 256>>>(0);
    k_rowcount<<<NND / 8, 256>>>(1);
    k_scan<<<1, 1024>>>(0);
    k_scan<<<1, 1024>>>(1);
    k_scan<<<1, 1024>>>(2);
    k_rowfill<<<NND / 8, 256>>>(0);
    k_rowfill<<<NND / 8, 256>>>(1);
    k_scatter<<<ETB, 256>>>(ei, E);

    k_a2<<<NND, 256>>>();
    k_outdegf<<<NND / 256, 256>>>();
    k_rowsum<<<NND, 256>>>();
    k_mw<<<ETB, 256>>>(ei, E);

    k_s1<<<(NND * 8 + 255) / 256, 256>>>(as1, ad1);
    k_attn1<<<NND, 256>>>(ei, E);
    k_agg1<<<NND, 256>>>(ei, b1, E);

    k_gemm2<<<dim3(256 / BN, NND / BM), 256>>>(W2);
    k_gemm3<<<dim3(256 / BN, NND / BM), 256>>>(resW2);

    k_s2<<<NND, 256>>>(as2, ad2);
    k_attn2<<<NND / 8, 256>>>(ei, E);
    k_agg2<<<NND, 256>>>(ei, b2, out, E);
}

// round 6
// speedup vs baseline: 1.2595x; 1.2595x over previous
#include <cuda_runtime.h>
#include <cstdint>

#define NND 4096
#define EMAX 131072
#define ETMAX (EMAX + NND)

// ---------------- device scratch ----------------
__device__ __align__(16) float g_h1[(size_t)NND * 512];
__device__ __align__(16) float g_hact[(size_t)NND * 512];
__device__ __align__(16) float g_h2[(size_t)NND * 256];
__device__ __align__(16) float g_res[(size_t)NND * 256];
__device__ __align__(16) unsigned char g_A[(size_t)NND * NND];
__device__ __align__(16) unsigned char g_AT[(size_t)NND * NND];
__device__ int g_degout[NND], g_degin[NND], g_degdst[NND], g_degsrc[NND];
__device__ int g_rpout[NND + 1], g_rpin[NND + 1], g_rpdst[NND + 1], g_rpsrc[NND + 1];
__device__ int g_colout[ETMAX + 64], g_colin[ETMAX + 64];
__device__ int g_eid[ETMAX + 64];    // raw edges sorted by dst
__device__ int g_eids[ETMAX + 64];   // raw edges sorted by src
__device__ int g_cnt[NND], g_cnt2[NND];
__device__ float g_mw[ETMAX];
__device__ float g_outdegf[NND];
__device__ float g_s1s[NND * 8], g_s1d[NND * 8];
__device__ float g_s2s[NND], g_s2d[NND];
__device__ float g_alpha1[(size_t)ETMAX * 8];
__device__ float g_alpha2[ETMAX];

// ---------------- zero fill (A, AT, counters only — no dense A2 anymore) ------
__global__ void k_zero() {
    size_t i0 = (size_t)blockIdx.x * blockDim.x + threadIdx.x;
    size_t stride = (size_t)gridDim.x * blockDim.x;
    int4 zi = make_int4(0, 0, 0, 0);
    int4* a = (int4*)g_A;
    for (size_t i = i0; i < (size_t)NND * NND / 16; i += stride) a[i] = zi;
    int4* at = (int4*)g_AT;
    for (size_t i = i0; i < (size_t)NND * NND / 16; i += stride) at[i] = zi;
    if (i0 < NND) { g_degdst[i0] = 0; g_degsrc[i0] = 0; g_cnt[i0] = 0; g_cnt2[i0] = 0; }
}

// ---------------- SGEMM: 128x128 tile, 8x8 per thread, 256 threads ------------
#define BM 128
#define BN 128
#define BK 16
__device__ __forceinline__ void sgemm_body(const float* __restrict__ A,
                                           const float* __restrict__ B,
                                           float* __restrict__ C,
                                           int N, int K, int bm, int bn) {
    __shared__ float As[BK][BM + 4];
    __shared__ float Bs[BK][BN];
    const int tid = threadIdx.x;
    const int tx = tid & 15, ty = tid >> 4;
    float acc[8][8];
#pragma unroll
    for (int i = 0; i < 8; i++)
#pragma unroll
        for (int j = 0; j < 8; j++) acc[i][j] = 0.f;

    for (int k0 = 0; k0 < K; k0 += BK) {
#pragma unroll
        for (int i = 0; i < 2; i++) {
            int idx = tid + 256 * i;
            int r = idx >> 2, kq = (idx & 3) * 4;
            float4 v = *(const float4*)&A[(size_t)(bm + r) * K + k0 + kq];
            As[kq + 0][r] = v.x; As[kq + 1][r] = v.y;
            As[kq + 2][r] = v.z; As[kq + 3][r] = v.w;
        }
#pragma unroll
        for (int i = 0; i < 2; i++) {
            int idx = tid + 256 * i;
            int r = idx >> 5, nq = (idx & 31) * 4;
            *(float4*)&Bs[r][nq] = *(const float4*)&B[(size_t)(k0 + r) * N + bn + nq];
        }
        __syncthreads();
#pragma unroll
        for (int kk = 0; kk < BK; kk++) {
            float av[8], bv[8];
            *(float4*)(av)     = *(float4*)&As[kk][ty * 8];
            *(float4*)(av + 4) = *(float4*)&As[kk][ty * 8 + 4];
            *(float4*)(bv)     = *(float4*)&Bs[kk][tx * 8];
            *(float4*)(bv + 4) = *(float4*)&Bs[kk][tx * 8 + 4];
#pragma unroll
            for (int i = 0; i < 8; i++)
#pragma unroll
                for (int j = 0; j < 8; j++) acc[i][j] += av[i] * bv[j];
        }
        __syncthreads();
    }
#pragma unroll
    for (int i = 0; i < 8; i++) {
        float* crow = &C[(size_t)(bm + ty * 8 + i) * N + bn + tx * 8];
        *(float4*)crow       = make_float4(acc[i][0], acc[i][1], acc[i][2], acc[i][3]);
        *(float4*)(crow + 4) = make_float4(acc[i][4], acc[i][5], acc[i][6], acc[i][7]);
    }
}

__global__ __launch_bounds__(256) void k_gemm1(const float* __restrict__ x,
                                               const float* __restrict__ W1) {
    sgemm_body(x, W1, g_h1, 512, 512, blockIdx.y * BM, blockIdx.x * BN);
}
// fused layer-2 linear + residual linear: blockIdx.x in [0,4): 0-1 -> W2/h2, 2-3 -> resW2/res
__global__ __launch_bounds__(256) void k_gemm23(const float* __restrict__ W2,
                                                const float* __restrict__ resW2) {
    int bx = blockIdx.x;
    const float* B = (bx < 2) ? W2 : resW2;
    float* C = (bx < 2) ? g_h2 : g_res;
    int bn = (bx & 1) * BN;
    sgemm_body(g_hact, B, C, 256, 512, blockIdx.y * BM, bn);
}

// ---------------- graph build (edge_index int32 [2, E]) ----------------
__global__ void k_edges(const int* __restrict__ ei, int E) {
    int e = blockIdx.x * blockDim.x + threadIdx.x;
    int ET = E + NND;
    if (e >= ET) return;
    int s, d;
    if (e < E) { s = ei[e] & (NND - 1); d = ei[E + e] & (NND - 1); }
    else       { s = e - E; d = s; }
    g_A[(size_t)s * NND + d] = 1;
    g_AT[(size_t)d * NND + s] = 1;
    atomicAdd(&g_degdst[d], 1);
    atomicAdd(&g_degsrc[s], 1);
}

__global__ void k_rowcount(int sel) {
    const unsigned char* M = sel ? g_AT : g_A;
    int* deg = sel ? g_degin : g_degout;
    int row = blockIdx.x * 8 + (threadIdx.x >> 5);
    int lane = threadIdx.x & 31;
    const uint32_t* r = (const uint32_t*)(M + (size_t)row * NND);
    int cnt = 0;
    for (int i = lane; i < NND / 4; i += 32) {
        uint32_t u = r[i];
        cnt += (int)((u * 0x01010101u) >> 24);
    }
#pragma unroll
    for (int o = 16; o; o >>= 1) cnt += __shfl_down_sync(~0u, cnt, o);
    if (!lane) deg[row] = cnt;
}

__global__ void k_scan(int sel) {
    const int* deg = (sel == 0) ? g_degout : (sel == 1) ? g_degin
                   : (sel == 2) ? g_degdst : g_degsrc;
    int* rp = (sel == 0) ? g_rpout : (sel == 1) ? g_rpin
            : (sel == 2) ? g_rpdst : g_rpsrc;
    __shared__ int sh[1024];
    int t = threadIdx.x;
    int a0 = deg[t * 4], a1 = deg[t * 4 + 1], a2 = deg[t * 4 + 2], a3 = deg[t * 4 + 3];
    int tot = a0 + a1 + a2 + a3;
    sh[t] = tot;
    __syncthreads();
    int val = tot;
    for (int off = 1; off < 1024; off <<= 1) {
        int x = (t >= off) ? sh[t - off] : 0;
        __syncthreads();
        val += x;
        sh[t] = val;
        __syncthreads();
    }
    int excl = val - tot;
    rp[t * 4] = excl;
    rp[t * 4 + 1] = excl + a0;
    rp[t * 4 + 2] = excl + a0 + a1;
    rp[t * 4 + 3] = excl + a0 + a1 + a2;
    if (t == 1023) rp[NND] = val;
}

__global__ void k_rowfill(int sel) {
    const unsigned char* M = sel ? g_AT : g_A;
    const int* rp = sel ? g_rpin : g_rpout;
    int* col = sel ? g_colin : g_colout;
    int row = blockIdx.x * 8 + (threadIdx.x >> 5);
    int lane = threadIdx.x & 31;
    const unsigned char* r = M + (size_t)row * NND;
    int base = rp[row];
    for (int i0 = 0; i0 < NND; i0 += 32) {
        int v = r[i0 + lane];
        unsigned mask = __ballot_sync(~0u, v != 0);
        if (v) col[base + __popc(mask & ((1u << lane) - 1u))] = i0 + lane;
        base += __popc(mask);
    }
}

__global__ void k_outdegf() {
    int i = blockIdx.x * blockDim.x + threadIdx.x;
    if (i < NND) g_outdegf[i] = (float)(g_rpout[i + 1] - g_rpout[i]);
}

__global__ void k_scatter(const int* __restrict__ ei, int E) {
    int e = blockIdx.x * blockDim.x + threadIdx.x;
    int ET = E + NND;
    if (e >= ET) return;
    int s, d;
    if (e < E) { s = ei[e] & (NND - 1); d = ei[E + e] & (NND - 1); }
    else       { s = e - E; d = s; }
    int pos = atomicAdd(&g_cnt[d], 1);
    g_eid[g_rpdst[d] + pos] = e;
    int pos2 = atomicAdd(&g_cnt2[s], 1);
    g_eids[g_rpsrc[s] + pos2] = e;
}

// ---------------- fused motif: per-src smem A2-row histogram --------------------
// For each src node s: cntr[l] = #(2-paths s->k->l), then
//   rs = max(1, sum_l cntr[l]*outdeg(l))  (= rowsum of m3 row s)
//   for each raw out-edge e=(s,d): mw[e] = (sum_{l in in(d)} cntr[l]) / rs
__global__ __launch_bounds__(256) void k_mw_fused(const int* __restrict__ ei, int E) {
    __shared__ int cntr[NND];
    __shared__ float shred[8];
    __shared__ float shrs;
    int s = blockIdx.x;
    int tid = threadIdx.x, lane = tid & 31, warp = tid >> 5;

    int4* c4 = (int4*)cntr;
#pragma unroll
    for (int i = tid; i < NND / 4; i += 256) c4[i] = make_int4(0, 0, 0, 0);
    __syncthreads();

    int ob = g_rpout[s], no = g_rpout[s + 1] - ob;
    for (int ki = warp; ki < no; ki += 8) {
        int k = g_colout[ob + ki];
        int lb = g_rpout[k], le = g_rpout[k + 1];
        for (int p = lb + lane; p < le; p += 32)
            atomicAdd(&cntr[g_colout[p]], 1);
    }
    __syncthreads();

    // rowsum of m3 row s
    float acc = 0.f;
    for (int l = tid; l < NND; l += 256) {
        int c = cntr[l];
        if (c) acc += (float)c * g_outdegf[l];
    }
#pragma unroll
    for (int o = 16; o; o >>= 1) acc += __shfl_xor_sync(~0u, acc, o);
    if (!lane) shred[warp] = acc;
    __syncthreads();
    if (tid == 0) {
        float t = 0.f;
#pragma unroll
        for (int w = 0; w < 8; w++) t += shred[w];
        shrs = fmaxf(t, 1.0f);
    }
    __syncthreads();
    float inv_rs = 1.0f / shrs;

    // per out-edge motif weight
    int eb = g_rpsrc[s], ee = g_rpsrc[s + 1];
    for (int i = eb + warp; i < ee; i += 8) {
        int e = g_eids[i];
        int d = (e < E) ? (ei[E + e] & (NND - 1)) : s;
        int pb = g_rpin[d], pe = g_rpin[d + 1];
        int m = 0;
        for (int p = pb + lane; p < pe; p += 32) m += cntr[g_colin[p]];
#pragma unroll
        for (int o = 16; o; o >>= 1) m += __shfl_xor_sync(~0u, m, o);
        if (!lane) g_mw[e] = (float)m * inv_rs;
    }
}

// ---------------- attention ----------------
__global__ void k_s1(const float* __restrict__ as1, const float* __restrict__ ad1) {
    int idx = blockIdx.x * blockDim.x + threadIdx.x;
    if (idx >= NND * 8) return;
    int n = idx >> 3, h = idx & 7;
    const float* hr = g_h1 + (size_t)n * 512 + h * 64;
    const float* a = as1 + h * 64;
    const float* ad = ad1 + h * 64;
    float s = 0.f, d = 0.f;
#pragma unroll
    for (int c = 0; c < 64; c++) { float v = hr[c]; s += v * a[c]; d += v * ad[c]; }
    g_s1s[idx] = s; g_s1d[idx] = d;
}

__device__ __forceinline__ float leaky(float x) { return x > 0.f ? x : 0.2f * x; }

__global__ void k_attn1(const int* __restrict__ ei, int E) {
    int n = blockIdx.x;
    int h = threadIdx.x >> 5, lane = threadIdx.x & 31;
    int b = g_rpdst[n], deg = g_rpdst[n + 1] - b;
    float sd = g_s1d[n * 8 + h];
    float m1 = -1e30f, m2 = -1e30f;
    for (int p = lane; p < deg; p += 32) {
        int e = g_eid[b + p];
        int s_ = (e < E) ? (ei[e] & (NND - 1)) : n;
        float ev = g_s1s[s_ * 8 + h] + sd;
        m1 = fmaxf(m1, leaky(ev));
        m2 = fmaxf(m2, leaky(ev * g_mw[e]));
    }
#pragma unroll
    for (int o = 16; o; o >>= 1) {
        m1 = fmaxf(m1, __shfl_xor_sync(~0u, m1, o));
        m2 = fmaxf(m2, __shfl_xor_sync(~0u, m2, o));
    }
    float S1 = 0.f, S2 = 0.f;
    for (int p = lane; p < deg; p += 32) {
        int e = g_eid[b + p];
        int s_ = (e < E) ? (ei[e] & (NND - 1)) : n;
        float ev = g_s1s[s_ * 8 + h] + sd;
        S1 += expf(leaky(ev) - m1);
        S2 += expf(leaky(ev * g_mw[e]) - m2);
    }
#pragma unroll
    for (int o = 16; o; o >>= 1) {
        S1 += __shfl_xor_sync(~0u, S1, o);
        S2 += __shfl_xor_sync(~0u, S2, o);
    }
    float r1 = 1.0f / (S1 + 1e-16f), r2 = 1.0f / (S2 + 1e-16f);
    for (int p = lane; p < deg; p += 32) {
        int e = g_eid[b + p];
        int s_ = (e < E) ? (ei[e] & (NND - 1)) : n;
        float ev = g_s1s[s_ * 8 + h] + sd;
        float a1 = expf(leaky(ev) - m1) * r1;
        float a2 = expf(leaky(ev * g_mw[e]) - m2) * r2;
        g_alpha1[(size_t)e * 8 + h] = 0.5f * a1 + 0.5f * a2;
    }
}

__global__ void k_agg1(const int* __restrict__ ei,
                       const float* __restrict__ b1, int E) {
    int n = blockIdx.x, t = threadIdx.x;
    int c = t * 2, h = c >> 6;
    float a0 = 0.f, a1v = 0.f;
    int b = g_rpdst[n], en = g_rpdst[n + 1];
    for (int p = b; p < en; p++) {
        int e = g_eid[p];
        int s_ = (e < E) ? (ei[e] & (NND - 1)) : n;
        float al = g_alpha1[(size_t)e * 8 + h];
        float2 v = *(const float2*)(g_h1 + (size_t)s_ * 512 + c);
        a0 += al * v.x; a1v += al * v.y;
    }
    a0 += b1[c]; a1v += b1[c + 1];
    g_hact[(size_t)n * 512 + c]     = a0  > 0.f ? a0  : expm1f(a0);
    g_hact[(size_t)n * 512 + c + 1] = a1v > 0.f ? a1v : expm1f(a1v);
}

__global__ void k_s2(const float* __restrict__ as2, const float* __restrict__ ad2) {
    int n = blockIdx.x, t = threadIdx.x;
    float v = g_h2[(size_t)n * 256 + t];
    __shared__ float shs[256], shd[256];
    shs[t] = v * as2[t]; shd[t] = v * ad2[t];
    __syncthreads();
    for (int o = 128; o; o >>= 1) {
        if (t < o) { shs[t] += shs[t + o]; shd[t] += shd[t + o]; }
        __syncthreads();
    }
    if (!t) { g_s2s[n] = shs[0]; g_s2d[n] = shd[0]; }
}

__global__ void k_attn2(const int* __restrict__ ei, int E) {
    int n = blockIdx.x * 8 + (threadIdx.x >> 5);
    int lane = threadIdx.x & 31;
    if (n >= NND) return;
    int b = g_rpdst[n], deg = g_rpdst[n + 1] - b;
    float sd = g_s2d[n];
    float m1 = -1e30f, m2 = -1e30f;
    for (int p = lane; p < deg; p += 32) {
        int e = g_eid[b + p];
        int s_ = (e < E) ? (ei[e] & (NND - 1)) : n;
        float ev = g_s2s[s_] + sd;
        m1 = fmaxf(m1, leaky(ev));
        m2 = fmaxf(m2, leaky(ev * g_mw[e]));
    }
#pragma unroll
    for (int o = 16; o; o >>= 1) {
        m1 = fmaxf(m1, __shfl_xor_sync(~0u, m1, o));
        m2 = fmaxf(m2, __shfl_xor_sync(~0u, m2, o));
    }
    float S1 = 0.f, S2 = 0.f;
    for (int p = lane; p < deg; p += 32) {
        int e = g_eid[b + p];
        int s_ = (e < E) ? (ei[e] & (NND - 1)) : n;
        float ev = g_s2s[s_] + sd;
        S1 += expf(leaky(ev) - m1);
        S2 += expf(leaky(ev * g_mw[e]) - m2);
    }
#pragma unroll
    for (int o = 16; o; o >>= 1) {
        S1 += __shfl_xor_sync(~0u, S1, o);
        S2 += __shfl_xor_sync(~0u, S2, o);
    }
    float r1 = 1.0f / (S1 + 1e-16f), r2 = 1.0f / (S2 + 1e-16f);
    for (int p = lane; p < deg; p += 32) {
        int e = g_eid[b + p];
        int s_ = (e < E) ? (ei[e] & (NND - 1)) : n;
        float ev = g_s2s[s_] + sd;
        float a1 = expf(leaky(ev) - m1) * r1;
        float a2 = expf(leaky(ev * g_mw[e]) - m2) * r2;
        g_alpha2[e] = 0.5f * a1 + 0.5f * a2;
    }
}

__global__ void k_agg2(const int* __restrict__ ei,
                       const float* __restrict__ b2, float* __restrict__ out, int E) {
    int n = blockIdx.x, t = threadIdx.x;
    float acc = 0.f;
    int b = g_rpdst[n], en = g_rpdst[n + 1];
    for (int p = b; p < en; p++) {
        int e = g_eid[p];
        int s_ = (e < E) ? (ei[e] & (NND - 1)) : n;
        acc += g_alpha2[e] * g_h2[(size_t)s_ * 256 + t];
    }
    out[(size_t)n * 256 + t] = acc + g_res[(size_t)n * 256 + t] + b2[t];
}

// ---------------- host ----------------
extern "C" void kernel_launch(void* const* d_in, const int* in_sizes, int n_in,
                              void* d_out, int out_size) {
    const float* x      = (const float*)d_in[0];
    const int* ei       = (const int*)d_in[1];
    const float* W1     = (const float*)d_in[2];
    const float* as1    = (const float*)d_in[3];
    const float* ad1    = (const float*)d_in[4];
    const float* b1     = (const float*)d_in[5];
    const float* W2     = (const float*)d_in[6];
    const float* as2    = (const float*)d_in[7];
    const float* ad2    = (const float*)d_in[8];
    const float* b2     = (const float*)d_in[9];
    const float* resW2  = (const float*)d_in[10];
    float* out = (float*)d_out;

    int E = in_sizes[1] / 2;
    if (E > EMAX) E = EMAX;
    int ET = E + NND;
    int ETB = (ET + 255) / 256;

    k_zero<<<2368, 256>>>();

    k_gemm1<<<dim3(512 / BN, NND / BM), 256>>>(x, W1);

    k_edges<<<ETB, 256>>>(ei, E);
    k_rowcount<<<NND / 8, 256>>>(0);
    k_rowcount<<<NND / 8, 256>>>(1);
    k_scan<<<1, 1024>>>(0);
    k_scan<<<1, 1024>>>(1);
    k_scan<<<1, 1024>>>(2);
    k_scan<<<1, 1024>>>(3);
    k_rowfill<<<NND / 8, 256>>>(0);
    k_rowfill<<<NND / 8, 256>>>(1);
    k_outdegf<<<NND / 256, 256>>>();
    k_scatter<<<ETB, 256>>>(ei, E);

    k_mw_fused<<<NND, 256>>>(ei, E);

    k_s1<<<(NND * 8 + 255) / 256, 256>>>(as1, ad1);
    k_attn1<<<NND, 256>>>(ei, E);
    k_agg1<<<NND, 256>>>(ei, b1, E);

    k_gemm23<<<dim3(4, NND / BM), 256>>>(W2, resW2);

    k_s2<<<NND, 256>>>(as2, ad2);
    k_attn2<<<NND / 8, 256>>>(ei, E);
    k_agg2<<<NND, 256>>>(ei, b2, out, E);
}

// round 7
// speedup vs baseline: 1.4093x; 1.1190x over previous
#include <cuda_runtime.h>
#include <cstdint>

#define NND 4096
#define EMAX 131072
#define ETMAX (EMAX + NND)
typedef unsigned long long u64;

// ---------------- device scratch ----------------
__device__ __align__(16) float g_h1[(size_t)NND * 512];
__device__ __align__(16) float g_hact[(size_t)NND * 512];
__device__ __align__(16) float g_h2[(size_t)NND * 256];
__device__ __align__(16) float g_res[(size_t)NND * 256];
__device__ __align__(16) unsigned char g_A[(size_t)NND * NND];
__device__ __align__(16) unsigned char g_AT[(size_t)NND * NND];
__device__ int g_degout[NND], g_degin[NND], g_degdst[NND], g_degsrc[NND];
__device__ int g_rpout[NND + 1], g_rpin[NND + 1], g_rpdst[NND + 1], g_rpsrc[NND + 1];
__device__ int g_colout[ETMAX + 64], g_colin[ETMAX + 64];
__device__ int g_eid[ETMAX + 64];    // raw edges sorted by dst
__device__ int g_eids[ETMAX + 64];   // raw edges sorted by src
__device__ int g_cnt[NND], g_cnt2[NND];
__device__ float g_mw[ETMAX];
__device__ float g_outdegf[NND];
__device__ float g_W[NND];           // W[k] = sum_{l in out(k)} outdeg(l)
__device__ float g_s1s[NND * 8], g_s1d[NND * 8];
__device__ float g_s2s[NND], g_s2d[NND];
__device__ float g_alpha1[(size_t)ETMAX * 8];
__device__ float g_alpha2[ETMAX];

// ---------------- zero fill ----------------
__global__ void k_zero() {
    size_t i0 = (size_t)blockIdx.x * blockDim.x + threadIdx.x;
    size_t stride = (size_t)gridDim.x * blockDim.x;
    int4 zi = make_int4(0, 0, 0, 0);
    int4* a = (int4*)g_A;
    for (size_t i = i0; i < (size_t)NND * NND / 16; i += stride) a[i] = zi;
    int4* at = (int4*)g_AT;
    for (size_t i = i0; i < (size_t)NND * NND / 16; i += stride) at[i] = zi;
    if (i0 < NND) { g_degdst[i0] = 0; g_degsrc[i0] = 0; g_cnt[i0] = 0; g_cnt2[i0] = 0; }
}

// ---------------- SGEMM: 128x128 tile, 8x8/thread, packed f32x2 FMA -----------
#define BM 128
#define BN 128
#define BK 16

__device__ __forceinline__ u64 pack2(float a, float b) {
    u64 r; asm("mov.b64 %0, {%1, %2};" : "=l"(r) : "f"(a), "f"(b)); return r;
}
#define FFMA2(d, a, b) \
    asm("fma.rn.f32x2 %0, %1, %2, %3;" : "=l"(d) : "l"(a), "l"(b), "l"(d))

__device__ __forceinline__ void sgemm_body(const float* __restrict__ A,
                                           const float* __restrict__ B,
                                           float* __restrict__ C,
                                           int N, int K, int bm, int bn) {
    __shared__ float As[BK][BM + 4];
    __shared__ __align__(16) float Bs[BK][BN];
    const int tid = threadIdx.x;
    const int tx = tid & 15, ty = tid >> 4;
    u64 acc[8][4];
#pragma unroll
    for (int i = 0; i < 8; i++)
#pragma unroll
        for (int j = 0; j < 4; j++) acc[i][j] = 0ull;  // {0.f, 0.f}

    for (int k0 = 0; k0 < K; k0 += BK) {
#pragma unroll
        for (int i = 0; i < 2; i++) {
            int idx = tid + 256 * i;
            int r = idx >> 2, kq = (idx & 3) * 4;
            float4 v = *(const float4*)&A[(size_t)(bm + r) * K + k0 + kq];
            As[kq + 0][r] = v.x; As[kq + 1][r] = v.y;
            As[kq + 2][r] = v.z; As[kq + 3][r] = v.w;
        }
#pragma unroll
        for (int i = 0; i < 2; i++) {
            int idx = tid + 256 * i;
            int r = idx >> 5, nq = (idx & 31) * 4;
            *(float4*)&Bs[r][nq] = *(const float4*)&B[(size_t)(k0 + r) * N + bn + nq];
        }
        __syncthreads();
#pragma unroll
        for (int kk = 0; kk < BK; kk++) {
            float av[8];
            *(float4*)(av)     = *(float4*)&As[kk][ty * 8];
            *(float4*)(av + 4) = *(float4*)&As[kk][ty * 8 + 4];
            ulonglong2 bq0 = *(ulonglong2*)&Bs[kk][tx * 8];
            ulonglong2 bq1 = *(ulonglong2*)&Bs[kk][tx * 8 + 4];
#pragma unroll
            for (int i = 0; i < 8; i++) {
                u64 aa = pack2(av[i], av[i]);
                FFMA2(acc[i][0], aa, bq0.x);
                FFMA2(acc[i][1], aa, bq0.y);
                FFMA2(acc[i][2], aa, bq1.x);
                FFMA2(acc[i][3], aa, bq1.y);
            }
        }
        __syncthreads();
    }
#pragma unroll
    for (int i = 0; i < 8; i++) {
        float* crow = &C[(size_t)(bm + ty * 8 + i) * N + bn + tx * 8];
        *(u64*)(crow)     = acc[i][0];
        *(u64*)(crow + 2) = acc[i][1];
        *(u64*)(crow + 4) = acc[i][2];
        *(u64*)(crow + 6) = acc[i][3];
    }
}

__global__ __launch_bounds__(256) void k_gemm1(const float* __restrict__ x,
                                               const float* __restrict__ W1) {
    sgemm_body(x, W1, g_h1, 512, 512, blockIdx.y * BM, blockIdx.x * BN);
}
__global__ __launch_bounds__(256) void k_gemm23(const float* __restrict__ W2,
                                                const float* __restrict__ resW2) {
    int bx = blockIdx.x;
    const float* B = (bx < 2) ? W2 : resW2;
    float* C = (bx < 2) ? g_h2 : g_res;
    int bn = (bx & 1) * BN;
    sgemm_body(g_hact, B, C, 256, 512, blockIdx.y * BM, bn);
}

// ---------------- graph build (edge_index int32 [2, E]) ----------------
__global__ void k_edges(const int* __restrict__ ei, int E) {
    int e = blockIdx.x * blockDim.x + threadIdx.x;
    int ET = E + NND;
    if (e >= ET) return;
    int s, d;
    if (e < E) { s = ei[e] & (NND - 1); d = ei[E + e] & (NND - 1); }
    else       { s = e - E; d = s; }
    g_A[(size_t)s * NND + d] = 1;
    g_AT[(size_t)d * NND + s] = 1;
    atomicAdd(&g_degdst[d], 1);
    atomicAdd(&g_degsrc[s], 1);
}

__global__ void k_rowcount() {
    int sel = blockIdx.y;
    const unsigned char* M = sel ? g_AT : g_A;
    int* deg = sel ? g_degin : g_degout;
    int row = blockIdx.x * 8 + (threadIdx.x >> 5);
    int lane = threadIdx.x & 31;
    const uint32_t* r = (const uint32_t*)(M + (size_t)row * NND);
    int cnt = 0;
    for (int i = lane; i < NND / 4; i += 32) {
        uint32_t u = r[i];
        cnt += (int)((u * 0x01010101u) >> 24);
    }
#pragma unroll
    for (int o = 16; o; o >>= 1) cnt += __shfl_down_sync(~0u, cnt, o);
    if (!lane) deg[row] = cnt;
}

// 4 scans in one launch (blockIdx.x = sel); sel==0 also emits outdegf
__global__ void k_scan_all() {
    int sel = blockIdx.x;
    const int* deg = (sel == 0) ? g_degout : (sel == 1) ? g_degin
                   : (sel == 2) ? g_degdst : g_degsrc;
    int* rp = (sel == 0) ? g_rpout : (sel == 1) ? g_rpin
            : (sel == 2) ? g_rpdst : g_rpsrc;
    __shared__ int sh[1024];
    int t = threadIdx.x;
    int a0 = deg[t * 4], a1 = deg[t * 4 + 1], a2 = deg[t * 4 + 2], a3 = deg[t * 4 + 3];
    if (sel == 0) {
        g_outdegf[t * 4] = (float)a0;     g_outdegf[t * 4 + 1] = (float)a1;
        g_outdegf[t * 4 + 2] = (float)a2; g_outdegf[t * 4 + 3] = (float)a3;
    }
    int tot = a0 + a1 + a2 + a3;
    sh[t] = tot;
    __syncthreads();
    int val = tot;
    for (int off = 1; off < 1024; off <<= 1) {
        int x = (t >= off) ? sh[t - off] : 0;
        __syncthreads();
        val += x;
        sh[t] = val;
        __syncthreads();
    }
    int excl = val - tot;
    rp[t * 4] = excl;
    rp[t * 4 + 1] = excl + a0;
    rp[t * 4 + 2] = excl + a0 + a1;
    rp[t * 4 + 3] = excl + a0 + a1 + a2;
    if (t == 1023) rp[NND] = val;
}

__global__ void k_rowfill() {
    int sel = blockIdx.y;
    const unsigned char* M = sel ? g_AT : g_A;
    const int* rp = sel ? g_rpin : g_rpout;
    int* col = sel ? g_colin : g_colout;
    int row = blockIdx.x * 8 + (threadIdx.x >> 5);
    int lane = threadIdx.x & 31;
    const unsigned char* r = M + (size_t)row * NND;
    int base = rp[row];
    for (int i0 = 0; i0 < NND; i0 += 32) {
        int v = r[i0 + lane];
        unsigned mask = __ballot_sync(~0u, v != 0);
        if (v) col[base + __popc(mask & ((1u << lane) - 1u))] = i0 + lane;
        base += __popc(mask);
    }
}

__global__ void k_scatter(const int* __restrict__ ei, int E) {
    int e = blockIdx.x * blockDim.x + threadIdx.x;
    int ET = E + NND;
    if (e >= ET) return;
    int s, d;
    if (e < E) { s = ei[e] & (NND - 1); d = ei[E + e] & (NND - 1); }
    else       { s = e - E; d = s; }
    int pos = atomicAdd(&g_cnt[d], 1);
    g_eid[g_rpdst[d] + pos] = e;
    int pos2 = atomicAdd(&g_cnt2[s], 1);
    g_eids[g_rpsrc[s] + pos2] = e;
}

// W[k] = sum_{l in out(k)} outdeg(l)  (integers -> exact fp32)
__global__ void k_wsum() {
    int n = blockIdx.x * 8 + (threadIdx.x >> 5);
    int lane = threadIdx.x & 31;
    int b = g_rpout[n], e = g_rpout[n + 1];
    float acc = 0.f;
    for (int p = b + lane; p < e; p += 32) acc += g_outdegf[g_colout[p]];
#pragma unroll
    for (int o = 16; o; o >>= 1) acc += __shfl_xor_sync(~0u, acc, o);
    if (!lane) g_W[n] = acc;
}

// ---------------- fused motif: per-src smem A2-row histogram -------------------
__global__ __launch_bounds__(256) void k_mw_fused(const int* __restrict__ ei, int E) {
    __shared__ int cntr[NND];
    __shared__ float shred[8];
    __shared__ float shrs;
    int s = blockIdx.x;
    int tid = threadIdx.x, lane = tid & 31, warp = tid >> 5;

    int4* c4 = (int4*)cntr;
#pragma unroll
    for (int i = tid; i < NND / 4; i += 256) c4[i] = make_int4(0, 0, 0, 0);
    __syncthreads();

    int ob = g_rpout[s], no = g_rpout[s + 1] - ob;
    float wacc = 0.f;
    for (int ki = warp; ki < no; ki += 8) {
        int k = g_colout[ob + ki];
        if (!lane) wacc += g_W[k];
        int lb = g_rpout[k], le = g_rpout[k + 1];
        for (int p = lb + lane; p < le; p += 32)
            atomicAdd(&cntr[g_colout[p]], 1);
    }
    if (!lane) shred[warp] = wacc;
    __syncthreads();
    if (tid == 0) {
        float t = 0.f;
#pragma unroll
        for (int w = 0; w < 8; w++) t += shred[w];
        shrs = fmaxf(t, 1.0f);
    }
    __syncthreads();
    float inv_rs = 1.0f / shrs;

    int eb = g_rpsrc[s], ee = g_rpsrc[s + 1];
    for (int i = eb + warp; i < ee; i += 8) {
        int e = g_eids[i];
        int d = (e < E) ? (ei[E + e] & (NND - 1)) : s;
        int pb = g_rpin[d], pe = g_rpin[d + 1];
        int m = 0;
        for (int p = pb + lane; p < pe; p += 32) m += cntr[g_colin[p]];
#pragma unroll
        for (int o = 16; o; o >>= 1) m += __shfl_xor_sync(~0u, m, o);
        if (!lane) g_mw[e] = (float)m * inv_rs;
    }
}

// ---------------- attention ----------------
__global__ void k_s1(const float* __restrict__ as1, const float* __restrict__ ad1) {
    int idx = blockIdx.x * blockDim.x + threadIdx.x;
    if (idx >= NND * 8) return;
    int n = idx >> 3, h = idx & 7;
    const float* hr = g_h1 + (size_t)n * 512 + h * 64;
    const float* a = as1 + h * 64;
    const float* ad = ad1 + h * 64;
    float s = 0.f, d = 0.f;
#pragma unroll
    for (int c = 0; c < 64; c++) { float v = hr[c]; s += v * a[c]; d += v * ad[c]; }
    g_s1s[idx] = s; g_s1d[idx] = d;
}

__device__ __forceinline__ float leaky(float x) { return x > 0.f ? x : 0.2f * x; }

__global__ void k_attn1(const int* __restrict__ ei, int E) {
    int n = blockIdx.x;
    int h = threadIdx.x >> 5, lane = threadIdx.x & 31;
    int b = g_rpdst[n], deg = g_rpdst[n + 1] - b;
    float sd = g_s1d[n * 8 + h];
    float m1 = -1e30f, m2 = -1e30f;
    for (int p = lane; p < deg; p += 32) {
        int e = g_eid[b + p];
        int s_ = (e < E) ? (ei[e] & (NND - 1)) : n;
        float ev = g_s1s[s_ * 8 + h] + sd;
        m1 = fmaxf(m1, leaky(ev));
        m2 = fmaxf(m2, leaky(ev * g_mw[e]));
    }
#pragma unroll
    for (int o = 16; o; o >>= 1) {
        m1 = fmaxf(m1, __shfl_xor_sync(~0u, m1, o));
        m2 = fmaxf(m2, __shfl_xor_sync(~0u, m2, o));
    }
    float S1 = 0.f, S2 = 0.f;
    for (int p = lane; p < deg; p += 32) {
        int e = g_eid[b + p];
        int s_ = (e < E) ? (ei[e] & (NND - 1)) : n;
        float ev = g_s1s[s_ * 8 + h] + sd;
        S1 += expf(leaky(ev) - m1);
        S2 += expf(leaky(ev * g_mw[e]) - m2);
    }
#pragma unroll
    for (int o = 16; o; o >>= 1) {
        S1 += __shfl_xor_sync(~0u, S1, o);
        S2 += __shfl_xor_sync(~0u, S2, o);
    }
    float r1 = 1.0f / (S1 + 1e-16f), r2 = 1.0f / (S2 + 1e-16f);
    for (int p = lane; p < deg; p += 32) {
        int e = g_eid[b + p];
        int s_ = (e < E) ? (ei[e] & (NND - 1)) : n;
        float ev = g_s1s[s_ * 8 + h] + sd;
        float a1 = expf(leaky(ev) - m1) * r1;
        float a2 = expf(leaky(ev * g_mw[e]) - m2) * r2;
        g_alpha1[(size_t)e * 8 + h] = 0.5f * a1 + 0.5f * a2;
    }
}

__global__ void k_agg1(const int* __restrict__ ei,
                       const float* __restrict__ b1, int E) {
    int n = blockIdx.x, t = threadIdx.x;
    int c = t * 2, h = c >> 6;
    float a0 = 0.f, a1v = 0.f;
    int b = g_rpdst[n], en = g_rpdst[n + 1];
    for (int p = b; p < en; p++) {
        int e = g_eid[p];
        int s_ = (e < E) ? (ei[e] & (NND - 1)) : n;
        float al = g_alpha1[(size_t)e * 8 + h];
        float2 v = *(const float2*)(g_h1 + (size_t)s_ * 512 + c);
        a0 += al * v.x; a1v += al * v.y;
    }
    a0 += b1[c]; a1v += b1[c + 1];
    g_hact[(size_t)n * 512 + c]     = a0  > 0.f ? a0  : expm1f(a0);
    g_hact[(size_t)n * 512 + c + 1] = a1v > 0.f ? a1v : expm1f(a1v);
}

__global__ void k_s2(const float* __restrict__ as2, const float* __restrict__ ad2) {
    int n = blockIdx.x, t = threadIdx.x;
    float v = g_h2[(size_t)n * 256 + t];
    __shared__ float shs[256], shd[256];
    shs[t] = v * as2[t]; shd[t] = v * ad2[t];
    __syncthreads();
    for (int o = 128; o; o >>= 1) {
        if (t < o) { shs[t] += shs[t + o]; shd[t] += shd[t + o]; }
        __syncthreads();
    }
    if (!t) { g_s2s[n] = shs[0]; g_s2d[n] = shd[0]; }
}

__global__ void k_attn2(const int* __restrict__ ei, int E) {
    int n = blockIdx.x * 8 + (threadIdx.x >> 5);
    int lane = threadIdx.x & 31;
    if (n >= NND) return;
    int b = g_rpdst[n], deg = g_rpdst[n + 1] - b;
    float sd = g_s2d[n];
    float m1 = -1e30f, m2 = -1e30f;
    for (int p = lane; p < deg; p += 32) {
        int e = g_eid[b + p];
        int s_ = (e < E) ? (ei[e] & (NND - 1)) : n;
        float ev = g_s2s[s_] + sd;
        m1 = fmaxf(m1, leaky(ev));
        m2 = fmaxf(m2, leaky(ev * g_mw[e]));
    }
#pragma unroll
    for (int o = 16; o; o >>= 1) {
        m1 = fmaxf(m1, __shfl_xor_sync(~0u, m1, o));
        m2 = fmaxf(m2, __shfl_xor_sync(~0u, m2, o));
    }
    float S1 = 0.f, S2 = 0.f;
    for (int p = lane; p < deg; p += 32) {
        int e = g_eid[b + p];
        int s_ = (e < E) ? (ei[e] & (NND - 1)) : n;
        float ev = g_s2s[s_] + sd;
        S1 += expf(leaky(ev) - m1);
        S2 += expf(leaky(ev * g_mw[e]) - m2);
    }
#pragma unroll
    for (int o = 16; o; o >>= 1) {
        S1 += __shfl_xor_sync(~0u, S1, o);
        S2 += __shfl_xor_sync(~0u, S2, o);
    }
    float r1 = 1.0f / (S1 + 1e-16f), r2 = 1.0f / (S2 + 1e-16f);
    for (int p = lane; p < deg; p += 32) {
        int e = g_eid[b + p];
        int s_ = (e < E) ? (ei[e] & (NND - 1)) : n;
        float ev = g_s2s[s_] + sd;
        float a1 = expf(leaky(ev) - m1) * r1;
        float a2 = expf(leaky(ev * g_mw[e]) - m2) * r2;
        g_alpha2[e] = 0.5f * a1 + 0.5f * a2;
    }
}

__global__ void k_agg2(const int* __restrict__ ei,
                       const float* __restrict__ b2, float* __restrict__ out, int E) {
    int n = blockIdx.x, t = threadIdx.x;
    float acc = 0.f;
    int b = g_rpdst[n], en = g_rpdst[n + 1];
    for (int p = b; p < en; p++) {
        int e = g_eid[p];
        int s_ = (e < E) ? (ei[e] & (NND - 1)) : n;
        acc += g_alpha2[e] * g_h2[(size_t)s_ * 256 + t];
    }
    out[(size_t)n * 256 + t] = acc + g_res[(size_t)n * 256 + t] + b2[t];
}

// ---------------- host ----------------
extern "C" void kernel_launch(void* const* d_in, const int* in_sizes, int n_in,
                              void* d_out, int out_size) {
    const float* x      = (const float*)d_in[0];
    const int* ei       = (const int*)d_in[1];
    const float* W1     = (const float*)d_in[2];
    const float* as1    = (const float*)d_in[3];
    const float* ad1    = (const float*)d_in[4];
    const float* b1     = (const float*)d_in[5];
    const float* W2     = (const float*)d_in[6];
    const float* as2    = (const float*)d_in[7];
    const float* ad2    = (const float*)d_in[8];
    const float* b2     = (const float*)d_in[9];
    const float* resW2  = (const float*)d_in[10];
    float* out = (float*)d_out;

    int E = in_sizes[1] / 2;
    if (E > EMAX) E = EMAX;
    int ET = E + NND;
    int ETB = (ET + 255) / 256;

    k_zero<<<2368, 256>>>();

    k_gemm1<<<dim3(512 / BN, NND / BM), 256>>>(x, W1);

    k_edges<<<ETB, 256>>>(ei, E);
    k_rowcount<<<dim3(NND / 8, 2), 256>>>();
    k_scan_all<<<4, 1024>>>();
    k_rowfill<<<dim3(NND / 8, 2), 256>>>();
    k_scatter<<<ETB, 256>>>(ei, E);
    k_wsum<<<NND / 8, 256>>>();

    k_mw_fused<<<NND, 256>>>(ei, E);

    k_s1<<<(NND * 8 + 255) / 256, 256>>>(as1, ad1);
    k_attn1<<<NND, 256>>>(ei, E);
    k_agg1<<<NND, 256>>>(ei, b1, E);

    k_gemm23<<<dim3(4, NND / BM), 256>>>(W2, resW2);

    k_s2<<<NND, 256>>>(as2, ad2);
    k_attn2<<<NND / 8, 256>>>(ei, E);
    k_agg2<<<NND, 256>>>(ei, b2, out, E);
}

// round 8
// speedup vs baseline: 1.7366x; 1.2323x over previous
#include <cuda_runtime.h>
#include <cstdint>

#define NND 4096
#define NWRD 128   /* 32-bit words per bitmap row */
#define EMAX 131072
#define ETMAX (EMAX + NND)
typedef unsigned long long u64;

// ---------------- device scratch ----------------
__device__ __align__(16) float g_h1[(size_t)NND * 512];
__device__ __align__(16) float g_hact[(size_t)NND * 512];
__device__ __align__(16) float g_h2[(size_t)NND * 256];
__device__ __align__(16) float g_res[(size_t)NND * 256];
__device__ __align__(16) uint32_t g_Ab[(size_t)NND * NWRD];   // out adjacency bitmap
__device__ __align__(16) uint32_t g_ATb[(size_t)NND * NWRD];  // in  adjacency bitmap
__device__ int g_degout[NND], g_degin[NND], g_degdst[NND], g_degsrc[NND];
__device__ int g_rpout[NND + 1], g_rpin[NND + 1], g_rpdst[NND + 1], g_rpsrc[NND + 1];
__device__ int g_colout[ETMAX + 64], g_colin[ETMAX + 64];
__device__ int g_eid[ETMAX + 64];
__device__ int g_eids[ETMAX + 64];
__device__ int g_cnt[NND], g_cnt2[NND];
__device__ float g_mw[ETMAX];
__device__ float g_outdegf[NND];
__device__ float g_W[NND];
__device__ float g_s1s[NND * 8], g_s1d[NND * 8];
__device__ float g_s2s[NND], g_s2d[NND];
__device__ float g_alpha1[(size_t)ETMAX * 8];
__device__ float g_alpha2[ETMAX];

// ---------------- zero fill (bitmaps + counters + score accumulators) ---------
__global__ void k_zero() {
    size_t i0 = (size_t)blockIdx.x * blockDim.x + threadIdx.x;
    size_t stride = (size_t)gridDim.x * blockDim.x;
    int4 zi = make_int4(0, 0, 0, 0);
    int4* a = (int4*)g_Ab;
    for (size_t i = i0; i < (size_t)NND * NWRD / 4; i += stride) a[i] = zi;
    int4* at = (int4*)g_ATb;
    for (size_t i = i0; i < (size_t)NND * NWRD / 4; i += stride) at[i] = zi;
    float4* s1 = (float4*)g_s1s;
    for (size_t i = i0; i < NND * 8 / 4; i += stride) s1[i] = make_float4(0, 0, 0, 0);
    float4* s1b = (float4*)g_s1d;
    for (size_t i = i0; i < NND * 8 / 4; i += stride) s1b[i] = make_float4(0, 0, 0, 0);
    if (i0 < NND) {
        g_degdst[i0] = 0; g_degsrc[i0] = 0; g_cnt[i0] = 0; g_cnt2[i0] = 0;
        g_s2s[i0] = 0.f; g_s2d[i0] = 0.f;
    }
}

// ---------------- SGEMM: 128x128, 8x8/thread, f32x2 FMA, double-buffered ------
#define BM 128
#define BN 128
#define BK 16

__device__ __forceinline__ u64 pack2(float a, float b) {
    u64 r; asm("mov.b64 %0, {%1, %2};" : "=l"(r) : "f"(a), "f"(b)); return r;
}
#define FFMA2(d, a, b) \
    asm("fma.rn.f32x2 %0, %1, %2, %3;" : "=l"(d) : "l"(a), "l"(b), "l"(d))
__device__ __forceinline__ void unpack2(u64 v, float& lo, float& hi) {
    asm("mov.b64 {%0, %1}, %2;" : "=f"(lo), "=f"(hi) : "l"(v));
}

// MODE: 0 = plain store, 1 = also accumulate s1 scores (layer1, per-head-64),
//       2 = also accumulate s2 scores (layer2, full row)
template <int MODE>
__device__ __forceinline__ void sgemm_body(const float* __restrict__ A,
                                           const float* __restrict__ B,
                                           float* __restrict__ C,
                                           const float* __restrict__ av1,
                                           const float* __restrict__ av2,
                                           float* __restrict__ os,
                                           float* __restrict__ od,
                                           int N, int K, int bm, int bn) {
    __shared__ float As[2][BK][BM + 4];
    __shared__ __align__(16) float Bs[2][BK][BN];
    const int tid = threadIdx.x;
    const int tx = tid & 15, ty = tid >> 4;
    const int ar = tid >> 2, akq = (tid & 3) * 4;
    const int br = tid >> 5, bq = (tid & 31) * 4;
    u64 acc[8][4];
#pragma unroll
    for (int i = 0; i < 8; i++)
#pragma unroll
        for (int j = 0; j < 4; j++) acc[i][j] = 0ull;

    const int nt = K / BK;
    float4 ra0, ra1, rb0, rb1;
    // preload tile 0
    ra0 = *(const float4*)&A[(size_t)(bm + ar) * K + akq];
    ra1 = *(const float4*)&A[(size_t)(bm + ar + 64) * K + akq];
    rb0 = *(const float4*)&B[(size_t)br * N + bn + bq];
    rb1 = *(const float4*)&B[(size_t)(br + 8) * N + bn + bq];
    {
        As[0][akq + 0][ar] = ra0.x; As[0][akq + 1][ar] = ra0.y;
        As[0][akq + 2][ar] = ra0.z; As[0][akq + 3][ar] = ra0.w;
        As[0][akq + 0][ar + 64] = ra1.x; As[0][akq + 1][ar + 64] = ra1.y;
        As[0][akq + 2][ar + 64] = ra1.z; As[0][akq + 3][ar + 64] = ra1.w;
        *(float4*)&Bs[0][br][bq] = rb0;
        *(float4*)&Bs[0][br + 8][bq] = rb1;
    }

    for (int kt = 0; kt < nt; kt++) {
        __syncthreads();
        int cur = kt & 1;
        if (kt + 1 < nt) {
            int k0 = (kt + 1) * BK;
            ra0 = *(const float4*)&A[(size_t)(bm + ar) * K + k0 + akq];
            ra1 = *(const float4*)&A[(size_t)(bm + ar + 64) * K + k0 + akq];
            rb0 = *(const float4*)&B[(size_t)(k0 + br) * N + bn + bq];
            rb1 = *(const float4*)&B[(size_t)(k0 + br + 8) * N + bn + bq];
        }
#pragma unroll
        for (int kk = 0; kk < BK; kk++) {
            float avr[8];
            *(float4*)(avr)     = *(float4*)&As[cur][kk][ty * 8];
            *(float4*)(avr + 4) = *(float4*)&As[cur][kk][ty * 8 + 4];
            ulonglong2 bq0 = *(ulonglong2*)&Bs[cur][kk][tx * 8];
            ulonglong2 bq1 = *(ulonglong2*)&Bs[cur][kk][tx * 8 + 4];
#pragma unroll
            for (int i = 0; i < 8; i++) {
                u64 aa = pack2(avr[i], avr[i]);
                FFMA2(acc[i][0], aa, bq0.x);
                FFMA2(acc[i][1], aa, bq0.y);
                FFMA2(acc[i][2], aa, bq1.x);
                FFMA2(acc[i][3], aa, bq1.y);
            }
        }
        if (kt + 1 < nt) {
            int nxt = cur ^ 1;
            As[nxt][akq + 0][ar] = ra0.x; As[nxt][akq + 1][ar] = ra0.y;
            As[nxt][akq + 2][ar] = ra0.z; As[nxt][akq + 3][ar] = ra0.w;
            As[nxt][akq + 0][ar + 64] = ra1.x; As[nxt][akq + 1][ar + 64] = ra1.y;
            As[nxt][akq + 2][ar + 64] = ra1.z; As[nxt][akq + 3][ar + 64] = ra1.w;
            *(float4*)&Bs[nxt][br][bq] = rb0;
            *(float4*)&Bs[nxt][br + 8][bq] = rb1;
        }
    }

    int col0 = bn + tx * 8;
    float a1v[8], a2v[8];
    if (MODE) {
        *(float4*)(a1v)     = *(const float4*)&av1[col0];
        *(float4*)(a1v + 4) = *(const float4*)&av1[col0 + 4];
        *(float4*)(a2v)     = *(const float4*)&av2[col0];
        *(float4*)(a2v + 4) = *(const float4*)&av2[col0 + 4];
    }
#pragma unroll
    for (int i = 0; i < 8; i++) {
        int row = bm + ty * 8 + i;
        float* crow = &C[(size_t)row * N + col0];
        *(u64*)(crow)     = acc[i][0];
        *(u64*)(crow + 2) = acc[i][1];
        *(u64*)(crow + 4) = acc[i][2];
        *(u64*)(crow + 6) = acc[i][3];
        if (MODE) {
            float c[8];
            unpack2(acc[i][0], c[0], c[1]); unpack2(acc[i][1], c[2], c[3]);
            unpack2(acc[i][2], c[4], c[5]); unpack2(acc[i][3], c[6], c[7]);
            float ps = 0.f, pd = 0.f;
#pragma unroll
            for (int j = 0; j < 8; j++) { ps += c[j] * a1v[j]; pd += c[j] * a2v[j]; }
            if (MODE == 1) {
                int h = col0 >> 6;
                atomicAdd(&os[row * 8 + h], ps);
                atomicAdd(&od[row * 8 + h], pd);
            } else {
                atomicAdd(&os[row], ps);
                atomicAdd(&od[row], pd);
            }
        }
    }
}

__global__ __launch_bounds__(256) void k_gemm1(const float* __restrict__ x,
                                               const float* __restrict__ W1,
                                               const float* __restrict__ as1,
                                               const float* __restrict__ ad1) {
    sgemm_body<1>(x, W1, g_h1, as1, ad1, g_s1s, g_s1d,
                  512, 512, blockIdx.y * BM, blockIdx.x * BN);
}
__global__ __launch_bounds__(256) void k_gemm23(const float* __restrict__ W2,
                                                const float* __restrict__ resW2,
                                                const float* __restrict__ as2,
                                                const float* __restrict__ ad2) {
    int bx = blockIdx.x;
    int bn = (bx & 1) * BN;
    if (bx < 2)
        sgemm_body<2>(g_hact, W2, g_h2, as2, ad2, g_s2s, g_s2d,
                      256, 512, blockIdx.y * BM, bn);
    else
        sgemm_body<0>(g_hact, resW2, g_res, nullptr, nullptr, nullptr, nullptr,
                      256, 512, blockIdx.y * BM, bn);
}

// ---------------- graph build ----------------
__global__ void k_edges(const int* __restrict__ ei, int E) {
    int e = blockIdx.x * blockDim.x + threadIdx.x;
    int ET = E + NND;
    if (e >= ET) return;
    int s, d;
    if (e < E) { s = ei[e] & (NND - 1); d = ei[E + e] & (NND - 1); }
    else       { s = e - E; d = s; }
    atomicOr(&g_Ab[s * NWRD + (d >> 5)], 1u << (d & 31));
    atomicOr(&g_ATb[d * NWRD + (s >> 5)], 1u << (s & 31));
    atomicAdd(&g_degdst[d], 1);
    atomicAdd(&g_degsrc[s], 1);
}

__global__ void k_rowcount() {
    int sel = blockIdx.y;
    const uint32_t* M = sel ? g_ATb : g_Ab;
    int* deg = sel ? g_degin : g_degout;
    int row = blockIdx.x * 8 + (threadIdx.x >> 5);
    int lane = threadIdx.x & 31;
    const uint32_t* r = M + (size_t)row * NWRD;
    int cnt = __popc(r[lane]) + __popc(r[lane + 32]) +
              __popc(r[lane + 64]) + __popc(r[lane + 96]);
#pragma unroll
    for (int o = 16; o; o >>= 1) cnt += __shfl_down_sync(~0u, cnt, o);
    if (!lane) deg[row] = cnt;
}

__global__ void k_scan_all() {
    int sel = blockIdx.x;
    const int* deg = (sel == 0) ? g_degout : (sel == 1) ? g_degin
                   : (sel == 2) ? g_degdst : g_degsrc;
    int* rp = (sel == 0) ? g_rpout : (sel == 1) ? g_rpin
            : (sel == 2) ? g_rpdst : g_rpsrc;
    __shared__ int sh[1024];
    int t = threadIdx.x;
    int a0 = deg[t * 4], a1 = deg[t * 4 + 1], a2 = deg[t * 4 + 2], a3 = deg[t * 4 + 3];
    if (sel == 0) {
        g_outdegf[t * 4] = (float)a0;     g_outdegf[t * 4 + 1] = (float)a1;
        g_outdegf[t * 4 + 2] = (float)a2; g_outdegf[t * 4 + 3] = (float)a3;
    }
    int tot = a0 + a1 + a2 + a3;
    sh[t] = tot;
    __syncthreads();
    int val = tot;
    for (int off = 1; off < 1024; off <<= 1) {
        int x = (t >= off) ? sh[t - off] : 0;
        __syncthreads();
        val += x;
        sh[t] = val;
        __syncthreads();
    }
    int excl = val - tot;
    rp[t * 4] = excl;
    rp[t * 4 + 1] = excl + a0;
    rp[t * 4 + 2] = excl + a0 + a1;
    rp[t * 4 + 3] = excl + a0 + a1 + a2;
    if (t == 1023) rp[NND] = val;
}

__global__ void k_rowfill() {
    int sel = blockIdx.y;
    const uint32_t* M = sel ? g_ATb : g_Ab;
    const int* rp = sel ? g_rpin : g_rpout;
    int* col = sel ? g_colin : g_colout;
    int row = blockIdx.x * 8 + (threadIdx.x >> 5);
    int lane = threadIdx.x & 31;
    const uint32_t* r = M + (size_t)row * NWRD;
    int base = rp[row];
#pragma unroll
    for (int wc = 0; wc < 4; wc++) {
        int widx = wc * 32 + lane;
        uint32_t w = r[widx];
        int pc = __popc(w);
        int off = pc;
#pragma unroll
        for (int o = 1; o < 32; o <<= 1) {
            int x = __shfl_up_sync(~0u, off, o);
            if (lane >= o) off += x;
        }
        int tot = __shfl_sync(~0u, off, 31);
        off -= pc;               // exclusive prefix
        int dst = base + off;
        uint32_t m = w;
        while (m) {
            int b = __ffs(m) - 1;
            col[dst++] = widx * 32 + b;
            m &= m - 1;
        }
        base += tot;
    }
}

__global__ void k_scatter(const int* __restrict__ ei, int E) {
    int e = blockIdx.x * blockDim.x + threadIdx.x;
    int ET = E + NND;
    if (e >= ET) return;
    int s, d;
    if (e < E) { s = ei[e] & (NND - 1); d = ei[E + e] & (NND - 1); }
    else       { s = e - E; d = s; }
    int pos = atomicAdd(&g_cnt[d], 1);
    g_eid[g_rpdst[d] + pos] = e;
    int pos2 = atomicAdd(&g_cnt2[s], 1);
    g_eids[g_rpsrc[s] + pos2] = e;
}

__global__ void k_wsum() {
    int n = blockIdx.x * 8 + (threadIdx.x >> 5);
    int lane = threadIdx.x & 31;
    int b = g_rpout[n], e = g_rpout[n + 1];
    float acc = 0.f;
    for (int p = b + lane; p < e; p += 32) acc += g_outdegf[g_colout[p]];
#pragma unroll
    for (int o = 16; o; o >>= 1) acc += __shfl_xor_sync(~0u, acc, o);
    if (!lane) g_W[n] = acc;
}

// ---------------- fused motif ----------------
__global__ __launch_bounds__(256) void k_mw_fused(const int* __restrict__ ei, int E) {
    __shared__ int cntr[NND];
    __shared__ float shred[8];
    __shared__ float shrs;
    int s = blockIdx.x;
    int tid = threadIdx.x, lane = tid & 31, warp = tid >> 5;

    int4* c4 = (int4*)cntr;
#pragma unroll
    for (int i = tid; i < NND / 4; i += 256) c4[i] = make_int4(0, 0, 0, 0);
    __syncthreads();

    int ob = g_rpout[s], no = g_rpout[s + 1] - ob;
    float wacc = 0.f;
    for (int ki = warp; ki < no; ki += 8) {
        int k = g_colout[ob + ki];
        if (!lane) wacc += g_W[k];
        int lb = g_rpout[k], le = g_rpout[k + 1];
        for (int p = lb + lane; p < le; p += 32)
            atomicAdd(&cntr[g_colout[p]], 1);
    }
    if (!lane) shred[warp] = wacc;
    __syncthreads();
    if (tid == 0) {
        float t = 0.f;
#pragma unroll
        for (int w = 0; w < 8; w++) t += shred[w];
        shrs = fmaxf(t, 1.0f);
    }
    __syncthreads();
    float inv_rs = 1.0f / shrs;

    int eb = g_rpsrc[s], ee = g_rpsrc[s + 1];
    for (int i = eb + warp; i < ee; i += 8) {
        int e = g_eids[i];
        int d = (e < E) ? (ei[E + e] & (NND - 1)) : s;
        int pb = g_rpin[d], pe = g_rpin[d + 1];
        int m = 0;
        for (int p = pb + lane; p < pe; p += 32) m += cntr[g_colin[p]];
#pragma unroll
        for (int o = 16; o; o >>= 1) m += __shfl_xor_sync(~0u, m, o);
        if (!lane) g_mw[e] = (float)m * inv_rs;
    }
}

// ---------------- attention (registers cache ev/mw across softmax passes) -----
__device__ __forceinline__ float leaky(float x) { return x > 0.f ? x : 0.2f * x; }
#define ECAP 4

__global__ void k_attn1(const int* __restrict__ ei, int E) {
    int n = blockIdx.x;
    int h = threadIdx.x >> 5, lane = threadIdx.x & 31;
    int b = g_rpdst[n], deg = g_rpdst[n + 1] - b;
    float sd = g_s1d[n * 8 + h];
    int nt = (deg + 31) >> 5;
    float cev[ECAP], cmw[ECAP];
    float m1 = -1e30f, m2 = -1e30f;
    for (int t = 0; t < nt; t++) {
        int p = t * 32 + lane;
        float ev = 0.f, mw = 0.f;
        if (p < deg) {
            int e = g_eid[b + p];
            int s_ = (e < E) ? (ei[e] & (NND - 1)) : n;
            ev = g_s1s[s_ * 8 + h] + sd;
            mw = g_mw[e];
            m1 = fmaxf(m1, leaky(ev));
            m2 = fmaxf(m2, leaky(ev * mw));
        }
        if (t < ECAP) { cev[t] = ev; cmw[t] = mw; }
    }
#pragma unroll
    for (int o = 16; o; o >>= 1) {
        m1 = fmaxf(m1, __shfl_xor_sync(~0u, m1, o));
        m2 = fmaxf(m2, __shfl_xor_sync(~0u, m2, o));
    }
    float S1 = 0.f, S2 = 0.f;
    for (int t = 0; t < nt; t++) {
        int p = t * 32 + lane;
        if (p < deg) {
            float ev, mw;
            if (t < ECAP) { ev = cev[t]; mw = cmw[t]; }
            else {
                int e = g_eid[b + p];
                int s_ = (e < E) ? (ei[e] & (NND - 1)) : n;
                ev = g_s1s[s_ * 8 + h] + sd; mw = g_mw[e];
            }
            S1 += expf(leaky(ev) - m1);
            S2 += expf(leaky(ev * mw) - m2);
        }
    }
#pragma unroll
    for (int o = 16; o; o >>= 1) {
        S1 += __shfl_xor_sync(~0u, S1, o);
        S2 += __shfl_xor_sync(~0u, S2, o);
    }
    float r1 = 1.0f / (S1 + 1e-16f), r2 = 1.0f / (S2 + 1e-16f);
    for (int t = 0; t < nt; t++) {
        int p = t * 32 + lane;
        if (p < deg) {
            int e = g_eid[b + p];
            float ev, mw;
            if (t < ECAP) { ev = cev[t]; mw = cmw[t]; }
            else {
                int s_ = (e < E) ? (ei[e] & (NND - 1)) : n;
                ev = g_s1s[s_ * 8 + h] + sd; mw = g_mw[e];
            }
            float a1 = expf(leaky(ev) - m1) * r1;
            float a2 = expf(leaky(ev * mw) - m2) * r2;
            g_alpha1[(size_t)e * 8 + h] = 0.5f * a1 + 0.5f * a2;
        }
    }
}

__global__ void k_agg1(const int* __restrict__ ei,
                       const float* __restrict__ b1, int E) {
    int n = blockIdx.x, t = threadIdx.x;
    int c = t * 2, h = c >> 6;
    float a0 = 0.f, a1v = 0.f;
    int b = g_rpdst[n], en = g_rpdst[n + 1];
    for (int p = b; p < en; p++) {
        int e = g_eid[p];
        int s_ = (e < E) ? (ei[e] & (NND - 1)) : n;
        float al = g_alpha1[(size_t)e * 8 + h];
        float2 v = *(const float2*)(g_h1 + (size_t)s_ * 512 + c);
        a0 += al * v.x; a1v += al * v.y;
    }
    a0 += b1[c]; a1v += b1[c + 1];
    g_hact[(size_t)n * 512 + c]     = a0  > 0.f ? a0  : expm1f(a0);
    g_hact[(size_t)n * 512 + c + 1] = a1v > 0.f ? a1v : expm1f(a1v);
}

__global__ void k_attn2(const int* __restrict__ ei, int E) {
    int n = blockIdx.x * 8 + (threadIdx.x >> 5);
    int lane = threadIdx.x & 31;
    if (n >= NND) return;
    int b = g_rpdst[n], deg = g_rpdst[n + 1] - b;
    float sd = g_s2d[n];
    int nt = (deg + 31) >> 5;
    float cev[ECAP], cmw[ECAP];
    float m1 = -1e30f, m2 = -1e30f;
    for (int t = 0; t < nt; t++) {
        int p = t * 32 + lane;
        float ev = 0.f, mw = 0.f;
        if (p < deg) {
            int e = g_eid[b + p];
            int s_ = (e < E) ? (ei[e] & (NND - 1)) : n;
            ev = g_s2s[s_] + sd;
            mw = g_mw[e];
            m1 = fmaxf(m1, leaky(ev));
            m2 = fmaxf(m2, leaky(ev * mw));
        }
        if (t < ECAP) { cev[t] = ev; cmw[t] = mw; }
    }
#pragma unroll
    for (int o = 16; o; o >>= 1) {
        m1 = fmaxf(m1, __shfl_xor_sync(~0u, m1, o));
        m2 = fmaxf(m2, __shfl_xor_sync(~0u, m2, o));
    }
    float S1 = 0.f, S2 = 0.f;
    for (int t = 0; t < nt; t++) {
        int p = t * 32 + lane;
        if (p < deg) {
            float ev, mw;
            if (t < ECAP) { ev = cev[t]; mw = cmw[t]; }
            else {
                int e = g_eid[b + p];
                int s_ = (e < E) ? (ei[e] & (NND - 1)) : n;
                ev = g_s2s[s_] + sd; mw = g_mw[e];
            }
            S1 += expf(leaky(ev) - m1);
            S2 += expf(leaky(ev * mw) - m2);
        }
    }
#pragma unroll
    for (int o = 16; o; o >>= 1) {
        S1 += __shfl_xor_sync(~0u, S1, o);
        S2 += __shfl_xor_sync(~0u, S2, o);
    }
    float r1 = 1.0f / (S1 + 1e-16f), r2 = 1.0f / (S2 + 1e-16f);
    for (int t = 0; t < nt; t++) {
        int p = t * 32 + lane;
        if (p < deg) {
            int e = g_eid[b + p];
            float ev, mw;
            if (t < ECAP) { ev = cev[t]; mw = cmw[t]; }
            else {
                int s_ = (e < E) ? (ei[e] & (NND - 1)) : n;
                ev = g_s2s[s_] + sd; mw = g_mw[e];
            }
            float a1 = expf(leaky(ev) - m1) * r1;
            float a2 = expf(leaky(ev * mw) - m2) * r2;
            g_alpha2[e] = 0.5f * a1 + 0.5f * a2;
        }
    }
}

__global__ void k_agg2(const int* __restrict__ ei,
                       const float* __restrict__ b2, float* __restrict__ out, int E) {
    int n = blockIdx.x, t = threadIdx.x;
    float acc = 0.f;
    int b = g_rpdst[n], en = g_rpdst[n + 1];
    for (int p = b; p < en; p++) {
        int e = g_eid[p];
        int s_ = (e < E) ? (ei[e] & (NND - 1)) : n;
        acc += g_alpha2[e] * g_h2[(size_t)s_ * 256 + t];
    }
    out[(size_t)n * 256 + t] = acc + g_res[(size_t)n * 256 + t] + b2[t];
}

// ---------------- host ----------------
extern "C" void kernel_launch(void* const* d_in, const int* in_sizes, int n_in,
                              void* d_out, int out_size) {
    const float* x      = (const float*)d_in[0];
    const int* ei       = (const int*)d_in[1];
    const float* W1     = (const float*)d_in[2];
    const float* as1    = (const float*)d_in[3];
    const float* ad1    = (const float*)d_in[4];
    const float* b1     = (const float*)d_in[5];
    const float* W2     = (const float*)d_in[6];
    const float* as2    = (const float*)d_in[7];
    const float* ad2    = (const float*)d_in[8];
    const float* b2     = (const float*)d_in[9];
    const float* resW2  = (const float*)d_in[10];
    float* out = (float*)d_out;

    int E = in_sizes[1] / 2;
    if (E > EMAX) E = EMAX;
    int ET = E + NND;
    int ETB = (ET + 255) / 256;

    k_zero<<<592, 256>>>();

    k_gemm1<<<dim3(512 / BN, NND / BM), 256>>>(x, W1, as1, ad1);

    k_edges<<<ETB, 256>>>(ei, E);
    k_rowcount<<<dim3(NND / 8, 2), 256>>>();
    k_scan_all<<<4, 1024>>>();
    k_rowfill<<<dim3(NND / 8, 2), 256>>>();
    k_scatter<<<ETB, 256>>>(ei, E);
    k_wsum<<<NND / 8, 256>>>();

    k_mw_fused<<<NND, 256>>>(ei, E);

    k_attn1<<<NND, 256>>>(ei, E);
    k_agg1<<<NND, 256>>>(ei, b1, E);

    k_gemm23<<<dim3(4, NND / BM), 256>>>(W2, resW2, as2, ad2);

    k_attn2<<<NND / 8, 256>>>(ei, E);
    k_agg2<<<NND, 256>>>(ei, b2, out, E);
}

// round 9
// speedup vs baseline: 1.9099x; 1.0997x over previous
#include <cuda_runtime.h>
#include <cstdint>

#define NND 4096
#define NWRD 128
#define EMAX 131072
#define ETMAX (EMAX + NND)
typedef unsigned long long u64;

// ---------------- device scratch ----------------
__device__ __align__(16) float g_h1[(size_t)NND * 512];
__device__ __align__(16) float g_hact[(size_t)NND * 512];
__device__ __align__(16) float g_h2[(size_t)NND * 256];
__device__ __align__(16) float g_res[(size_t)NND * 256];
__device__ __align__(16) uint32_t g_Ab[(size_t)NND * NWRD];
__device__ __align__(16) uint32_t g_ATb[(size_t)NND * NWRD];
__device__ int g_degout[NND], g_degin[NND], g_degdst[NND], g_degsrc[NND];
__device__ int g_rpout[NND + 1], g_rpin[NND + 1], g_rpdst[NND + 1], g_rpsrc[NND + 1];
__device__ int g_colout[ETMAX + 64], g_colin[ETMAX + 64];
__device__ int g_srcd[ETMAX + 64];   // src node per dst-CSR position
__device__ int g_posd[ETMAX + 64];   // dst-CSR position of raw edge e
__device__ int g_eids[ETMAX + 64];   // raw edges sorted by src
__device__ int g_cnt[NND], g_cnt2[NND];
__device__ float g_mwd[ETMAX + 64];  // motif weight per dst-CSR position
__device__ float g_outdegf[NND];
__device__ float g_W[NND];
__device__ float g_s1s[NND * 8], g_s1d[NND * 8];
__device__ float g_s2s[NND], g_s2d[NND];
__device__ __align__(16) float g_alpha1[(size_t)(ETMAX + 64) * 8]; // by dst position
__device__ float g_alpha2[ETMAX + 64];                             // by dst position

// ---------------- zero fill ----------------
__global__ void k_zero() {
    size_t i0 = (size_t)blockIdx.x * blockDim.x + threadIdx.x;
    size_t stride = (size_t)gridDim.x * blockDim.x;
    int4 zi = make_int4(0, 0, 0, 0);
    int4* a = (int4*)g_Ab;
    for (size_t i = i0; i < (size_t)NND * NWRD / 4; i += stride) a[i] = zi;
    int4* at = (int4*)g_ATb;
    for (size_t i = i0; i < (size_t)NND * NWRD / 4; i += stride) at[i] = zi;
    float4* s1 = (float4*)g_s1s;
    for (size_t i = i0; i < NND * 8 / 4; i += stride) s1[i] = make_float4(0, 0, 0, 0);
    float4* s1b = (float4*)g_s1d;
    for (size_t i = i0; i < NND * 8 / 4; i += stride) s1b[i] = make_float4(0, 0, 0, 0);
    if (i0 < NND) {
        g_degdst[i0] = 0; g_degsrc[i0] = 0; g_cnt[i0] = 0; g_cnt2[i0] = 0;
        g_s2s[i0] = 0.f; g_s2d[i0] = 0.f;
    }
}

// ---------------- SGEMM: 128x128, 8x8/thread, f32x2 FMA, double-buffered ------
#define BM 128
#define BN 128
#define BK 16

__device__ __forceinline__ u64 pack2(float a, float b) {
    u64 r; asm("mov.b64 %0, {%1, %2};" : "=l"(r) : "f"(a), "f"(b)); return r;
}
#define FFMA2(d, a, b) \
    asm("fma.rn.f32x2 %0, %1, %2, %3;" : "=l"(d) : "l"(a), "l"(b), "l"(d))
__device__ __forceinline__ void unpack2(u64 v, float& lo, float& hi) {
    asm("mov.b64 {%0, %1}, %2;" : "=f"(lo), "=f"(hi) : "l"(v));
}

template <int MODE>
__device__ __forceinline__ void sgemm_body(const float* __restrict__ A,
                                           const float* __restrict__ B,
                                           float* __restrict__ C,
                                           const float* __restrict__ av1,
                                           const float* __restrict__ av2,
                                           float* __restrict__ os,
                                           float* __restrict__ od,
                                           int N, int K, int bm, int bn) {
    __shared__ float As[2][BK][BM + 4];
    __shared__ __align__(16) float Bs[2][BK][BN];
    const int tid = threadIdx.x;
    const int tx = tid & 15, ty = tid >> 4;
    const int ar = tid >> 2, akq = (tid & 3) * 4;
    const int br = tid >> 5, bq = (tid & 31) * 4;
    u64 acc[8][4];
#pragma unroll
    for (int i = 0; i < 8; i++)
#pragma unroll
        for (int j = 0; j < 4; j++) acc[i][j] = 0ull;

    const int nt = K / BK;
    float4 ra0, ra1, rb0, rb1;
    ra0 = *(const float4*)&A[(size_t)(bm + ar) * K + akq];
    ra1 = *(const float4*)&A[(size_t)(bm + ar + 64) * K + akq];
    rb0 = *(const float4*)&B[(size_t)br * N + bn + bq];
    rb1 = *(const float4*)&B[(size_t)(br + 8) * N + bn + bq];
    {
        As[0][akq + 0][ar] = ra0.x; As[0][akq + 1][ar] = ra0.y;
        As[0][akq + 2][ar] = ra0.z; As[0][akq + 3][ar] = ra0.w;
        As[0][akq + 0][ar + 64] = ra1.x; As[0][akq + 1][ar + 64] = ra1.y;
        As[0][akq + 2][ar + 64] = ra1.z; As[0][akq + 3][ar + 64] = ra1.w;
        *(float4*)&Bs[0][br][bq] = rb0;
        *(float4*)&Bs[0][br + 8][bq] = rb1;
    }

    for (int kt = 0; kt < nt; kt++) {
        __syncthreads();
        int cur = kt & 1;
        if (kt + 1 < nt) {
            int k0 = (kt + 1) * BK;
            ra0 = *(const float4*)&A[(size_t)(bm + ar) * K + k0 + akq];
            ra1 = *(const float4*)&A[(size_t)(bm + ar + 64) * K + k0 + akq];
            rb0 = *(const float4*)&B[(size_t)(k0 + br) * N + bn + bq];
            rb1 = *(const float4*)&B[(size_t)(k0 + br + 8) * N + bn + bq];
        }
#pragma unroll
        for (int kk = 0; kk < BK; kk++) {
            float avr[8];
            *(float4*)(avr)     = *(float4*)&As[cur][kk][ty * 8];
            *(float4*)(avr + 4) = *(float4*)&As[cur][kk][ty * 8 + 4];
            ulonglong2 bq0 = *(ulonglong2*)&Bs[cur][kk][tx * 8];
            ulonglong2 bq1 = *(ulonglong2*)&Bs[cur][kk][tx * 8 + 4];
#pragma unroll
            for (int i = 0; i < 8; i++) {
                u64 aa = pack2(avr[i], avr[i]);
                FFMA2(acc[i][0], aa, bq0.x);
                FFMA2(acc[i][1], aa, bq0.y);
                FFMA2(acc[i][2], aa, bq1.x);
                FFMA2(acc[i][3], aa, bq1.y);
            }
        }
        if (kt + 1 < nt) {
            int nxt = cur ^ 1;
            As[nxt][akq + 0][ar] = ra0.x; As[nxt][akq + 1][ar] = ra0.y;
            As[nxt][akq + 2][ar] = ra0.z; As[nxt][akq + 3][ar] = ra0.w;
            As[nxt][akq + 0][ar + 64] = ra1.x; As[nxt][akq + 1][ar + 64] = ra1.y;
            As[nxt][akq + 2][ar + 64] = ra1.z; As[nxt][akq + 3][ar + 64] = ra1.w;
            *(float4*)&Bs[nxt][br][bq] = rb0;
            *(float4*)&Bs[nxt][br + 8][bq] = rb1;
        }
    }

    int col0 = bn + tx * 8;
    float a1v[8], a2v[8];
    if (MODE) {
        *(float4*)(a1v)     = *(const float4*)&av1[col0];
        *(float4*)(a1v + 4) = *(const float4*)&av1[col0 + 4];
        *(float4*)(a2v)     = *(const float4*)&av2[col0];
        *(float4*)(a2v + 4) = *(const float4*)&av2[col0 + 4];
    }
#pragma unroll
    for (int i = 0; i < 8; i++) {
        int row = bm + ty * 8 + i;
        float* crow = &C[(size_t)row * N + col0];
        *(u64*)(crow)     = acc[i][0];
        *(u64*)(crow + 2) = acc[i][1];
        *(u64*)(crow + 4) = acc[i][2];
        *(u64*)(crow + 6) = acc[i][3];
        if (MODE) {
            float c[8];
            unpack2(acc[i][0], c[0], c[1]); unpack2(acc[i][1], c[2], c[3]);
            unpack2(acc[i][2], c[4], c[5]); unpack2(acc[i][3], c[6], c[7]);
            float ps = 0.f, pd = 0.f;
#pragma unroll
            for (int j = 0; j < 8; j++) { ps += c[j] * a1v[j]; pd += c[j] * a2v[j]; }
            if (MODE == 1) {
                int h = col0 >> 6;
                atomicAdd(&os[row * 8 + h], ps);
                atomicAdd(&od[row * 8 + h], pd);
            } else {
                atomicAdd(&os[row], ps);
                atomicAdd(&od[row], pd);
            }
        }
    }
}

__global__ __launch_bounds__(256) void k_gemm1(const float* __restrict__ x,
                                               const float* __restrict__ W1,
                                               const float* __restrict__ as1,
                                               const float* __restrict__ ad1) {
    sgemm_body<1>(x, W1, g_h1, as1, ad1, g_s1s, g_s1d,
                  512, 512, blockIdx.y * BM, blockIdx.x * BN);
}
__global__ __launch_bounds__(256) void k_gemm23(const float* __restrict__ W2,
                                                const float* __restrict__ resW2,
                                                const float* __restrict__ as2,
                                                const float* __restrict__ ad2) {
    int bx = blockIdx.x;
    int bn = (bx & 1) * BN;
    if (bx < 2)
        sgemm_body<2>(g_hact, W2, g_h2, as2, ad2, g_s2s, g_s2d,
                      256, 512, blockIdx.y * BM, bn);
    else
        sgemm_body<0>(g_hact, resW2, g_res, nullptr, nullptr, nullptr, nullptr,
                      256, 512, blockIdx.y * BM, bn);
}

// ---------------- graph build ----------------
__global__ void k_edges(const int* __restrict__ ei, int E) {
    int e = blockIdx.x * blockDim.x + threadIdx.x;
    int ET = E + NND;
    if (e >= ET) return;
    int s, d;
    if (e < E) { s = ei[e] & (NND - 1); d = ei[E + e] & (NND - 1); }
    else       { s = e - E; d = s; }
    atomicOr(&g_Ab[s * NWRD + (d >> 5)], 1u << (d & 31));
    atomicOr(&g_ATb[d * NWRD + (s >> 5)], 1u << (s & 31));
    atomicAdd(&g_degdst[d], 1);
    atomicAdd(&g_degsrc[s], 1);
}

__global__ void k_rowcount() {
    int sel = blockIdx.y;
    const uint32_t* M = sel ? g_ATb : g_Ab;
    int* deg = sel ? g_degin : g_degout;
    int row = blockIdx.x * 8 + (threadIdx.x >> 5);
    int lane = threadIdx.x & 31;
    const uint32_t* r = M + (size_t)row * NWRD;
    int cnt = __popc(r[lane]) + __popc(r[lane + 32]) +
              __popc(r[lane + 64]) + __popc(r[lane + 96]);
#pragma unroll
    for (int o = 16; o; o >>= 1) cnt += __shfl_down_sync(~0u, cnt, o);
    if (!lane) deg[row] = cnt;
}

__global__ void k_scan_all() {
    int sel = blockIdx.x;
    const int* deg = (sel == 0) ? g_degout : (sel == 1) ? g_degin
                   : (sel == 2) ? g_degdst : g_degsrc;
    int* rp = (sel == 0) ? g_rpout : (sel == 1) ? g_rpin
            : (sel == 2) ? g_rpdst : g_rpsrc;
    __shared__ int sh[1024];
    int t = threadIdx.x;
    int a0 = deg[t * 4], a1 = deg[t * 4 + 1], a2 = deg[t * 4 + 2], a3 = deg[t * 4 + 3];
    if (sel == 0) {
        g_outdegf[t * 4] = (float)a0;     g_outdegf[t * 4 + 1] = (float)a1;
        g_outdegf[t * 4 + 2] = (float)a2; g_outdegf[t * 4 + 3] = (float)a3;
    }
    int tot = a0 + a1 + a2 + a3;
    sh[t] = tot;
    __syncthreads();
    int val = tot;
    for (int off = 1; off < 1024; off <<= 1) {
        int x = (t >= off) ? sh[t - off] : 0;
        __syncthreads();
        val += x;
        sh[t] = val;
        __syncthreads();
    }
    int excl = val - tot;
    rp[t * 4] = excl;
    rp[t * 4 + 1] = excl + a0;
    rp[t * 4 + 2] = excl + a0 + a1;
    rp[t * 4 + 3] = excl + a0 + a1 + a2;
    if (t == 1023) rp[NND] = val;
}

__global__ void k_rowfill() {
    int sel = blockIdx.y;
    const uint32_t* M = sel ? g_ATb : g_Ab;
    const int* rp = sel ? g_rpin : g_rpout;
    int* col = sel ? g_colin : g_colout;
    int row = blockIdx.x * 8 + (threadIdx.x >> 5);
    int lane = threadIdx.x & 31;
    const uint32_t* r = M + (size_t)row * NWRD;
    int base = rp[row];
#pragma unroll
    for (int wc = 0; wc < 4; wc++) {
        int widx = wc * 32 + lane;
        uint32_t w = r[widx];
        int pc = __popc(w);
        int off = pc;
#pragma unroll
        for (int o = 1; o < 32; o <<= 1) {
            int x = __shfl_up_sync(~0u, off, o);
            if (lane >= o) off += x;
        }
        int tot = __shfl_sync(~0u, off, 31);
        off -= pc;
        int dst = base + off;
        uint32_t m = w;
        while (m) {
            int b = __ffs(m) - 1;
            col[dst++] = widx * 32 + b;
            m &= m - 1;
        }
        base += tot;
    }
}

// scatter raw edges into dst/src CSR; also (tail blocks) compute W[k]
__global__ void k_scatter(const int* __restrict__ ei, int E, int ETB) {
    if ((int)blockIdx.x < ETB) {
        int e = blockIdx.x * blockDim.x + threadIdx.x;
        int ET = E + NND;
        if (e >= ET) return;
        int s, d;
        if (e < E) { s = ei[e] & (NND - 1); d = ei[E + e] & (NND - 1); }
        else       { s = e - E; d = s; }
        int pos = atomicAdd(&g_cnt[d], 1);
        int dp = g_rpdst[d] + pos;
        g_srcd[dp] = s;
        g_posd[e] = dp;
        int pos2 = atomicAdd(&g_cnt2[s], 1);
        g_eids[g_rpsrc[s] + pos2] = e;
    } else {
        int n = (blockIdx.x - ETB) * 8 + (threadIdx.x >> 5);
        int lane = threadIdx.x & 31;
        int b = g_rpout[n], e = g_rpout[n + 1];
        float acc = 0.f;
        for (int p = b + lane; p < e; p += 32) acc += g_outdegf[g_colout[p]];
#pragma unroll
        for (int o = 16; o; o >>= 1) acc += __shfl_xor_sync(~0u, acc, o);
        if (!lane) g_W[n] = acc;
    }
}

// ---------------- fused motif (writes mw by dst position) ----------------
__global__ __launch_bounds__(256) void k_mw_fused(const int* __restrict__ ei, int E) {
    __shared__ int cntr[NND];
    __shared__ float shred[8];
    __shared__ float shrs;
    int s = blockIdx.x;
    int tid = threadIdx.x, lane = tid & 31, warp = tid >> 5;

    int4* c4 = (int4*)cntr;
#pragma unroll
    for (int i = tid; i < NND / 4; i += 256) c4[i] = make_int4(0, 0, 0, 0);
    __syncthreads();

    int ob = g_rpout[s], no = g_rpout[s + 1] - ob;
    float wacc = 0.f;
    for (int ki = warp; ki < no; ki += 8) {
        int k = g_colout[ob + ki];
        if (!lane) wacc += g_W[k];
        int lb = g_rpout[k], le = g_rpout[k + 1];
        for (int p = lb + lane; p < le; p += 32)
            atomicAdd(&cntr[g_colout[p]], 1);
    }
    if (!lane) shred[warp] = wacc;
    __syncthreads();
    if (tid == 0) {
        float t = 0.f;
#pragma unroll
        for (int w = 0; w < 8; w++) t += shred[w];
        shrs = fmaxf(t, 1.0f);
    }
    __syncthreads();
    float inv_rs = 1.0f / shrs;

    int eb = g_rpsrc[s], ee = g_rpsrc[s + 1];
    for (int i = eb + warp; i < ee; i += 8) {
        int e = g_eids[i];
        int d = (e < E) ? (ei[E + e] & (NND - 1)) : s;
        int pb = g_rpin[d], pe = g_rpin[d + 1];
        int m = 0;
        for (int p = pb + lane; p < pe; p += 32) m += cntr[g_colin[p]];
#pragma unroll
        for (int o = 16; o; o >>= 1) m += __shfl_xor_sync(~0u, m, o);
        if (!lane) g_mwd[g_posd[e]] = (float)m * inv_rs;
    }
}

// ---------------- attention (position-indexed, fully coalesced) ----------------
__device__ __forceinline__ float leaky(float x) { return x > 0.f ? x : 0.2f * x; }
#define ECAP 4

__global__ void k_attn1() {
    int n = blockIdx.x;
    int h = threadIdx.x >> 5, lane = threadIdx.x & 31;
    int b = g_rpdst[n], deg = g_rpdst[n + 1] - b;
    float sd = g_s1d[n * 8 + h];
    int nt = (deg + 31) >> 5;
    float cev[ECAP], cmw[ECAP];
    float m1 = -1e30f, m2 = -1e30f;
    for (int t = 0; t < nt; t++) {
        int p = t * 32 + lane;
        float ev = 0.f, mw = 0.f;
        if (p < deg) {
            int s_ = g_srcd[b + p];
            ev = g_s1s[s_ * 8 + h] + sd;
            mw = g_mwd[b + p];
            m1 = fmaxf(m1, leaky(ev));
            m2 = fmaxf(m2, leaky(ev * mw));
        }
        if (t < ECAP) { cev[t] = ev; cmw[t] = mw; }
    }
#pragma unroll
    for (int o = 16; o; o >>= 1) {
        m1 = fmaxf(m1, __shfl_xor_sync(~0u, m1, o));
        m2 = fmaxf(m2, __shfl_xor_sync(~0u, m2, o));
    }
    float S1 = 0.f, S2 = 0.f;
    for (int t = 0; t < nt; t++) {
        int p = t * 32 + lane;
        if (p < deg) {
            float ev, mw;
            if (t < ECAP) { ev = cev[t]; mw = cmw[t]; }
            else { ev = g_s1s[g_srcd[b + p] * 8 + h] + sd; mw = g_mwd[b + p]; }
            S1 += expf(leaky(ev) - m1);
            S2 += expf(leaky(ev * mw) - m2);
        }
    }
#pragma unroll
    for (int o = 16; o; o >>= 1) {
        S1 += __shfl_xor_sync(~0u, S1, o);
        S2 += __shfl_xor_sync(~0u, S2, o);
    }
    float r1 = 1.0f / (S1 + 1e-16f), r2 = 1.0f / (S2 + 1e-16f);
    for (int t = 0; t < nt; t++) {
        int p = t * 32 + lane;
        if (p < deg) {
            float ev, mw;
            if (t < ECAP) { ev = cev[t]; mw = cmw[t]; }
            else { ev = g_s1s[g_srcd[b + p] * 8 + h] + sd; mw = g_mwd[b + p]; }
            float a1 = expf(leaky(ev) - m1) * r1;
            float a2 = expf(leaky(ev * mw) - m2) * r2;
            g_alpha1[(size_t)(b + p) * 8 + h] = 0.5f * a1 + 0.5f * a2;
        }
    }
}

__global__ void k_agg1(const float* __restrict__ b1) {
    int n = blockIdx.x, t = threadIdx.x;
    int c = t * 2, h = c >> 6;
    u64 acc = 0ull;
    int b = g_rpdst[n], en = g_rpdst[n + 1];
    int p = b;
    for (; p + 1 < en; p += 2) {
        int s0 = g_srcd[p], s1 = g_srcd[p + 1];
        float al0 = g_alpha1[(size_t)p * 8 + h];
        float al1 = g_alpha1[(size_t)(p + 1) * 8 + h];
        u64 v0 = *(const u64*)(g_h1 + (size_t)s0 * 512 + c);
        u64 v1 = *(const u64*)(g_h1 + (size_t)s1 * 512 + c);
        FFMA2(acc, pack2(al0, al0), v0);
        FFMA2(acc, pack2(al1, al1), v1);
    }
    if (p < en) {
        int s0 = g_srcd[p];
        float al0 = g_alpha1[(size_t)p * 8 + h];
        u64 v0 = *(const u64*)(g_h1 + (size_t)s0 * 512 + c);
        FFMA2(acc, pack2(al0, al0), v0);
    }
    float a0, a1v;
    unpack2(acc, a0, a1v);
    a0 += b1[c]; a1v += b1[c + 1];
    g_hact[(size_t)n * 512 + c]     = a0  > 0.f ? a0  : expm1f(a0);
    g_hact[(size_t)n * 512 + c + 1] = a1v > 0.f ? a1v : expm1f(a1v);
}

__global__ void k_attn2() {
    int n = blockIdx.x * 8 + (threadIdx.x >> 5);
    int lane = threadIdx.x & 31;
    if (n >= NND) return;
    int b = g_rpdst[n], deg = g_rpdst[n + 1] - b;
    float sd = g_s2d[n];
    int nt = (deg + 31) >> 5;
    float cev[ECAP], cmw[ECAP];
    float m1 = -1e30f, m2 = -1e30f;
    for (int t = 0; t < nt; t++) {
        int p = t * 32 + lane;
        float ev = 0.f, mw = 0.f;
        if (p < deg) {
            ev = g_s2s[g_srcd[b + p]] + sd;
            mw = g_mwd[b + p];
            m1 = fmaxf(m1, leaky(ev));
            m2 = fmaxf(m2, leaky(ev * mw));
        }
        if (t < ECAP) { cev[t] = ev; cmw[t] = mw; }
    }
#pragma unroll
    for (int o = 16; o; o >>= 1) {
        m1 = fmaxf(m1, __shfl_xor_sync(~0u, m1, o));
        m2 = fmaxf(m2, __shfl_xor_sync(~0u, m2, o));
    }
    float S1 = 0.f, S2 = 0.f;
    for (int t = 0; t < nt; t++) {
        int p = t * 32 + lane;
        if (p < deg) {
            float ev, mw;
            if (t < ECAP) { ev = cev[t]; mw = cmw[t]; }
            else { ev = g_s2s[g_srcd[b + p]] + sd; mw = g_mwd[b + p]; }
            S1 += expf(leaky(ev) - m1);
            S2 += expf(leaky(ev * mw) - m2);
        }
    }
#pragma unroll
    for (int o = 16; o; o >>= 1) {
        S1 += __shfl_xor_sync(~0u, S1, o);
        S2 += __shfl_xor_sync(~0u, S2, o);
    }
    float r1 = 1.0f / (S1 + 1e-16f), r2 = 1.0f / (S2 + 1e-16f);
    for (int t = 0; t < nt; t++) {
        int p = t * 32 + lane;
        if (p < deg) {
            float ev, mw;
            if (t < ECAP) { ev = cev[t]; mw = cmw[t]; }
            else { ev = g_s2s[g_srcd[b + p]] + sd; mw = g_mwd[b + p]; }
            float a1 = expf(leaky(ev) - m1) * r1;
            float a2 = expf(leaky(ev * mw) - m2) * r2;
            g_alpha2[b + p] = 0.5f * a1 + 0.5f * a2;
        }
    }
}

__global__ void k_agg2(const float* __restrict__ b2, float* __restrict__ out) {
    int n = blockIdx.x, t = threadIdx.x;
    float acc = 0.f;
    int b = g_rpdst[n], en = g_rpdst[n + 1];
    int p = b;
    for (; p + 1 < en; p += 2) {
        int s0 = g_srcd[p], s1 = g_srcd[p + 1];
        float al0 = g_alpha2[p], al1 = g_alpha2[p + 1];
        float v0 = g_h2[(size_t)s0 * 256 + t];
        float v1 = g_h2[(size_t)s1 * 256 + t];
        acc += al0 * v0 + al1 * v1;
    }
    if (p < en) acc += g_alpha2[p] * g_h2[(size_t)g_srcd[p] * 256 + t];
    out[(size_t)n * 256 + t] = acc + g_res[(size_t)n * 256 + t] + b2[t];
}

// ---------------- host ----------------
extern "C" void kernel_launch(void* const* d_in, const int* in_sizes, int n_in,
                              void* d_out, int out_size) {
    const float* x      = (const float*)d_in[0];
    const int* ei       = (const int*)d_in[1];
    const float* W1     = (const float*)d_in[2];
    const float* as1    = (const float*)d_in[3];
    const float* ad1    = (const float*)d_in[4];
    const float* b1     = (const float*)d_in[5];
    const float* W2     = (const float*)d_in[6];
    const float* as2    = (const float*)d_in[7];
    const float* ad2    = (const float*)d_in[8];
    const float* b2     = (const float*)d_in[9];
    const float* resW2  = (const float*)d_in[10];
    float* out = (float*)d_out;

    int E = in_sizes[1] / 2;
    if (E > EMAX) E = EMAX;
    int ET = E + NND;
    int ETB = (ET + 255) / 256;

    k_zero<<<592, 256>>>();

    k_gemm1<<<dim3(512 / BN, NND / BM), 256>>>(x, W1, as1, ad1);

    k_edges<<<ETB, 256>>>(ei, E);
    k_rowcount<<<dim3(NND / 8, 2), 256>>>();
    k_scan_all<<<4, 1024>>>();
    k_rowfill<<<dim3(NND / 8, 2), 256>>>();
    k_scatter<<<ETB + NND / 8, 256>>>(ei, E, ETB);

    k_mw_fused<<<NND, 256>>>(ei, E);

    k_attn1<<<NND, 256>>>();
    k_agg1<<<NND, 256>>>(b1);

    k_gemm23<<<dim3(4, NND / BM), 256>>>(W2, resW2, as2, ad2);

    k_attn2<<<NND / 8, 256>>>();
    k_agg2<<<NND, 256>>>(b2, out);
}